// round 1
// baseline (speedup 1.0000x reference)
#include <cuda_runtime.h>
#include <cuda_bf16.h>

// ---------------- problem constants ----------------
#define Bdim 2
#define Tdim 2048
#define Cdim 2048
#define Hn   16
#define HD   128
#define Mrows (Bdim * Tdim)   // 4096
#define Ncols (3 * Cdim)      // 6144
#define Kdim  Cdim            // 2048

// ---------------- device scratch (no runtime alloc allowed) ----------------
__device__ float g_qkv[(size_t)Mrows * Ncols];  // ~100.7 MB
__device__ int   g_idx[Mrows];
__device__ float g_top1[Mrows];
__device__ float g_ksh[Mrows * HD];
__device__ float g_vsh[Mrows * HD];

// ---------------- helpers ----------------
__device__ __forceinline__ unsigned f2tf(float x) {
    unsigned r;
    asm("cvt.rna.tf32.f32 %0, %1;" : "=r"(r) : "f"(x));
    return r;
}

__device__ __forceinline__ void mma_tf32(float* c, const unsigned* a, const unsigned* b) {
    asm volatile(
        "mma.sync.aligned.m16n8k8.row.col.f32.tf32.tf32.f32 "
        "{%0,%1,%2,%3}, {%4,%5,%6,%7}, {%8,%9}, {%0,%1,%2,%3};"
        : "+f"(c[0]), "+f"(c[1]), "+f"(c[2]), "+f"(c[3])
        : "r"(a[0]), "r"(a[1]), "r"(a[2]), "r"(a[3]), "r"(b[0]), "r"(b[1]));
}

// ============================================================================
// Kernel 1: gating logits (fp32 exact) -> argmax + top-1 softmax value
// One block handles 8 tokens; 16 warps, warp h computes logit for head h.
// ============================================================================
#define GATE_TOKS 8
__global__ __launch_bounds__(512) void gate_kernel(const float* __restrict__ x,
                                                   const float* __restrict__ Wg) {
    const int wid = threadIdx.x >> 5, lane = threadIdx.x & 31;
    __shared__ float sl[Hn];
    const float* wr = Wg + (size_t)wid * Cdim;
    const int m0 = blockIdx.x * GATE_TOKS;
    for (int tm = 0; tm < GATE_TOKS; tm++) {
        const int m = m0 + tm;
        const float* xr = x + (size_t)m * Cdim;
        float s = 0.f;
        #pragma unroll 8
        for (int k = lane; k < Cdim; k += 32) s += xr[k] * wr[k];
        #pragma unroll
        for (int o = 16; o; o >>= 1) s += __shfl_xor_sync(0xffffffffu, s, o);
        if (lane == 0) sl[wid] = s;
        __syncthreads();
        if (threadIdx.x == 0) {
            float mx = sl[0]; int bi = 0;
            #pragma unroll
            for (int h = 1; h < Hn; h++) { if (sl[h] > mx) { mx = sl[h]; bi = h; } }
            float den = 0.f;
            #pragma unroll
            for (int h = 0; h < Hn; h++) den += __expf(sl[h] - mx);
            g_idx[m]  = bi;
            g_top1[m] = 1.f / den;   // = exp(mx)/sum(exp) = top-1 softmax value
        }
        __syncthreads();
    }
}

// ============================================================================
// Kernel 2: QKV GEMM  out[m,n] = sum_k x[m,k] * Wqkv[n,k]   (TF32 mma)
// BM=128 BN=128 BK=32, 256 threads, 8 warps (2x4), warp tile 64x32.
// ============================================================================
__global__ __launch_bounds__(256) void qkv_gemm(const float* __restrict__ X,
                                                const float* __restrict__ W) {
    __shared__ unsigned As[128][36];
    __shared__ unsigned Bs[128][36];
    const int tid = threadIdx.x;
    const int wid = tid >> 5, lane = tid & 31;
    const int grp = lane >> 2, qd = lane & 3;
    const int wm = (wid >> 2) * 64;   // 0 / 64
    const int wn = (wid & 3) * 32;    // 0..96
    const int m0 = blockIdx.y * 128, n0 = blockIdx.x * 128;

    float acc[4][4][4];
    #pragma unroll
    for (int mt = 0; mt < 4; mt++)
        #pragma unroll
        for (int nt = 0; nt < 4; nt++)
            #pragma unroll
            for (int r = 0; r < 4; r++) acc[mt][nt][r] = 0.f;

    for (int kt = 0; kt < Kdim; kt += 32) {
        #pragma unroll
        for (int i = 0; i < 4; i++) {
            int idx = tid + i * 256;           // 0..1023
            int r = idx >> 3, c = (idx & 7) << 2;
            float4 va = *(const float4*)(X + (size_t)(m0 + r) * Kdim + kt + c);
            As[r][c + 0] = f2tf(va.x); As[r][c + 1] = f2tf(va.y);
            As[r][c + 2] = f2tf(va.z); As[r][c + 3] = f2tf(va.w);
            float4 vb = *(const float4*)(W + (size_t)(n0 + r) * Kdim + kt + c);
            Bs[r][c + 0] = f2tf(vb.x); Bs[r][c + 1] = f2tf(vb.y);
            Bs[r][c + 2] = f2tf(vb.z); Bs[r][c + 3] = f2tf(vb.w);
        }
        __syncthreads();
        #pragma unroll
        for (int ks = 0; ks < 32; ks += 8) {
            unsigned a[4][4], b[4][2];
            #pragma unroll
            for (int mt = 0; mt < 4; mt++) {
                int rb = wm + mt * 16;
                a[mt][0] = As[rb + grp][ks + qd];
                a[mt][1] = As[rb + grp + 8][ks + qd];
                a[mt][2] = As[rb + grp][ks + qd + 4];
                a[mt][3] = As[rb + grp + 8][ks + qd + 4];
            }
            #pragma unroll
            for (int nt = 0; nt < 4; nt++) {
                int nb = wn + nt * 8;
                b[nt][0] = Bs[nb + grp][ks + qd];
                b[nt][1] = Bs[nb + grp][ks + qd + 4];
            }
            #pragma unroll
            for (int mt = 0; mt < 4; mt++)
                #pragma unroll
                for (int nt = 0; nt < 4; nt++)
                    mma_tf32(acc[mt][nt], a[mt], b[nt]);
        }
        __syncthreads();
    }
    // epilogue
    #pragma unroll
    for (int mt = 0; mt < 4; mt++) {
        int r0 = m0 + wm + mt * 16 + grp;
        #pragma unroll
        for (int nt = 0; nt < 4; nt++) {
            int cc = n0 + wn + nt * 8 + 2 * qd;
            *(float2*)(g_qkv + (size_t)r0 * Ncols + cc) =
                make_float2(acc[mt][nt][0], acc[mt][nt][1]);
            *(float2*)(g_qkv + (size_t)(r0 + 8) * Ncols + cc) =
                make_float2(acc[mt][nt][2], acc[mt][nt][3]);
        }
    }
}

// ============================================================================
// Kernel 3: select shared K/V head per token
// ============================================================================
__global__ __launch_bounds__(256) void select_kernel() {
    int i = blockIdx.x * 256 + threadIdx.x;       // 0 .. Mrows*HD-1
    int m = i >> 7, d = i & 127;
    int hsel = g_idx[m];
    const float* base = g_qkv + (size_t)m * Ncols;
    g_ksh[i] = base[Cdim + hsel * HD + d];
    g_vsh[i] = g_top1[m] * base[2 * Cdim + hsel * HD + d];
}

// ============================================================================
// Kernel 4: causal flash attention (TF32 mma for QK^T and PV)
// BQ=128 (8 warps x 16 rows), BKV=64, hd=128. P staged through SMEM per warp.
// ============================================================================
#define BQ  128
#define BKV 64
#define QST 132
#define KST 132
#define VST 136
#define PST 68
#define SMEM_WORDS (BQ * QST + BKV * KST + BKV * VST + 8 * 16 * PST)

__global__ __launch_bounds__(256, 1) void attn_kernel(float* __restrict__ out) {
    extern __shared__ unsigned sm[];
    unsigned* Qs = sm;
    unsigned* Ks = Qs + BQ * QST;
    unsigned* Vs = Ks + BKV * KST;
    unsigned* Ps = Vs + BKV * VST;

    const int qt = gridDim.x - 1 - blockIdx.x;    // heavy (late) tiles start first
    const int bh = blockIdx.y;
    const int b = bh >> 4, h = bh & 15;
    const int qbase = qt * BQ;
    const int tid = threadIdx.x, wid = tid >> 5, lane = tid & 31;
    const int grp = lane >> 2, qd = lane & 3;

    // load Q tile (fp32 -> tf32 bits)
    const float* qg = g_qkv + (size_t)(b * Tdim + qbase) * Ncols + h * HD;
    #pragma unroll
    for (int i = 0; i < 16; i++) {
        int idx = tid + i * 256;                  // 4096 float4s? no: 4096 total, r=idx/32
        int r = idx >> 5, c = (idx & 31) << 2;
        float4 v = *(const float4*)(qg + (size_t)r * Ncols + c);
        unsigned* dst = Qs + r * QST + c;
        dst[0] = f2tf(v.x); dst[1] = f2tf(v.y); dst[2] = f2tf(v.z); dst[3] = f2tf(v.w);
    }

    float o[16][4];
    #pragma unroll
    for (int n = 0; n < 16; n++)
        #pragma unroll
        for (int r = 0; r < 4; r++) o[n][r] = 0.f;
    float mi0 = -1e30f, mi1 = -1e30f, li0 = 0.f, li1 = 0.f;

    const float* kg = g_ksh + (size_t)b * Tdim * HD;
    const float* vg = g_vsh + (size_t)b * Tdim * HD;
    const int qrow_last = qbase + wid * 16 + 15;
    const int ntiles = (qbase + BQ) / BKV;
    const float sc = 0.08838834764831845f;        // 1/sqrt(128)

    for (int t = 0; t < ntiles; t++) {
        const int kstart = t * BKV;
        __syncthreads();                          // protect prev-iter smem reads
        #pragma unroll
        for (int i = 0; i < 8; i++) {
            int idx = tid + i * 256;              // 2048 float4s = 64x128
            int r = idx >> 5, c = (idx & 31) << 2;
            float4 kv = *(const float4*)(kg + (size_t)(kstart + r) * HD + c);
            unsigned* kd = Ks + r * KST + c;
            kd[0] = f2tf(kv.x); kd[1] = f2tf(kv.y); kd[2] = f2tf(kv.z); kd[3] = f2tf(kv.w);
            float4 vv = *(const float4*)(vg + (size_t)(kstart + r) * HD + c);
            unsigned* vd = Vs + r * VST + c;
            vd[0] = f2tf(vv.x); vd[1] = f2tf(vv.y); vd[2] = f2tf(vv.z); vd[3] = f2tf(vv.w);
        }
        __syncthreads();

        if (kstart <= qrow_last) {                // warp-uniform causal skip
            float s[8][4];
            #pragma unroll
            for (int n = 0; n < 8; n++)
                #pragma unroll
                for (int r = 0; r < 4; r++) s[n][r] = 0.f;

            // S = Q @ K^T  (k = head dim, 16 steps of 8)
            #pragma unroll
            for (int kk = 0; kk < 16; kk++) {
                unsigned a[4];
                const unsigned* qb = Qs + (wid * 16) * QST + kk * 8;
                a[0] = qb[grp * QST + qd];
                a[1] = qb[(grp + 8) * QST + qd];
                a[2] = qb[grp * QST + qd + 4];
                a[3] = qb[(grp + 8) * QST + qd + 4];
                #pragma unroll
                for (int nt = 0; nt < 8; nt++) {
                    unsigned bb[2];
                    bb[0] = Ks[(nt * 8 + grp) * KST + kk * 8 + qd];
                    bb[1] = Ks[(nt * 8 + grp) * KST + kk * 8 + qd + 4];
                    mma_tf32(s[nt], a, bb);
                }
            }

            // scale + causal mask
            const int row0 = qbase + wid * 16 + grp;
            const int row1 = row0 + 8;
            #pragma unroll
            for (int nt = 0; nt < 8; nt++) {
                int cbase = kstart + nt * 8 + 2 * qd;
                s[nt][0] = (cbase     <= row0) ? s[nt][0] * sc : -1e30f;
                s[nt][1] = (cbase + 1 <= row0) ? s[nt][1] * sc : -1e30f;
                s[nt][2] = (cbase     <= row1) ? s[nt][2] * sc : -1e30f;
                s[nt][3] = (cbase + 1 <= row1) ? s[nt][3] * sc : -1e30f;
            }

            // online softmax (rows grp and grp+8 of this warp's 16)
            float rm0 = -1e30f, rm1 = -1e30f;
            #pragma unroll
            for (int nt = 0; nt < 8; nt++) {
                rm0 = fmaxf(rm0, fmaxf(s[nt][0], s[nt][1]));
                rm1 = fmaxf(rm1, fmaxf(s[nt][2], s[nt][3]));
            }
            #pragma unroll
            for (int off = 1; off < 4; off <<= 1) {
                rm0 = fmaxf(rm0, __shfl_xor_sync(0xffffffffu, rm0, off));
                rm1 = fmaxf(rm1, __shfl_xor_sync(0xffffffffu, rm1, off));
            }
            const float mn0 = fmaxf(mi0, rm0), mn1 = fmaxf(mi1, rm1);
            const float f0 = __expf(mi0 - mn0), f1 = __expf(mi1 - mn1);
            mi0 = mn0; mi1 = mn1;

            float ls0 = 0.f, ls1 = 0.f;
            unsigned* pw = Ps + wid * 16 * PST;
            #pragma unroll
            for (int nt = 0; nt < 8; nt++) {
                float p0 = __expf(s[nt][0] - mn0), p1 = __expf(s[nt][1] - mn0);
                float p2 = __expf(s[nt][2] - mn1), p3 = __expf(s[nt][3] - mn1);
                ls0 += p0 + p1; ls1 += p2 + p3;
                int c = nt * 8 + 2 * qd;
                pw[grp * PST + c]           = f2tf(p0);
                pw[grp * PST + c + 1]       = f2tf(p1);
                pw[(grp + 8) * PST + c]     = f2tf(p2);
                pw[(grp + 8) * PST + c + 1] = f2tf(p3);
            }
            #pragma unroll
            for (int off = 1; off < 4; off <<= 1) {
                ls0 += __shfl_xor_sync(0xffffffffu, ls0, off);
                ls1 += __shfl_xor_sync(0xffffffffu, ls1, off);
            }
            li0 = li0 * f0 + ls0;
            li1 = li1 * f1 + ls1;
            #pragma unroll
            for (int nt = 0; nt < 16; nt++) {
                o[nt][0] *= f0; o[nt][1] *= f0;
                o[nt][2] *= f1; o[nt][3] *= f1;
            }
            __syncwarp();

            // O += P @ V  (k = key dim, 8 steps of 8; n = head dim, 16 tiles)
            #pragma unroll
            for (int kk = 0; kk < 8; kk++) {
                unsigned a[4];
                a[0] = pw[grp * PST + kk * 8 + qd];
                a[1] = pw[(grp + 8) * PST + kk * 8 + qd];
                a[2] = pw[grp * PST + kk * 8 + qd + 4];
                a[3] = pw[(grp + 8) * PST + kk * 8 + qd + 4];
                #pragma unroll
                for (int nt = 0; nt < 16; nt++) {
                    unsigned bb[2];
                    bb[0] = Vs[(kk * 8 + qd) * VST + nt * 8 + grp];
                    bb[1] = Vs[(kk * 8 + qd + 4) * VST + nt * 8 + grp];
                    mma_tf32(o[nt], a, bb);
                }
            }
        }
    }

    // normalize + write: out[b, t, h*HD + d]
    const float inv0 = 1.f / li0, inv1 = 1.f / li1;
    const size_t r0 = (size_t)(b * Tdim + qbase + wid * 16 + grp) * Cdim;
    const size_t r1 = r0 + (size_t)8 * Cdim;
    #pragma unroll
    for (int nt = 0; nt < 16; nt++) {
        int c = h * HD + nt * 8 + 2 * qd;
        *(float2*)(out + r0 + c) = make_float2(o[nt][0] * inv0, o[nt][1] * inv0);
        *(float2*)(out + r1 + c) = make_float2(o[nt][2] * inv1, o[nt][3] * inv1);
    }
}

// ============================================================================
// host launcher
// ============================================================================
extern "C" void kernel_launch(void* const* d_in, const int* in_sizes, int n_in,
                              void* d_out, int out_size) {
    const float* x    = (const float*)d_in[0];
    const float* Wg   = (const float*)d_in[1];
    const float* Wqkv = (const float*)d_in[2];
    float* out = (float*)d_out;

    gate_kernel<<<Mrows / GATE_TOKS, 512>>>(x, Wg);

    dim3 gg(Ncols / 128, Mrows / 128);
    qkv_gemm<<<gg, 256>>>(x, Wqkv);

    select_kernel<<<(Mrows * HD) / 256, 256>>>();

    size_t smem = (size_t)SMEM_WORDS * sizeof(unsigned);   // ~167 KB
    cudaFuncSetAttribute(attn_kernel, cudaFuncAttributeMaxDynamicSharedMemorySize, (int)smem);
    dim3 ga(Tdim / BQ, Bdim * Hn);
    attn_kernel<<<ga, 256, smem>>>(out);
}

// round 2
// speedup vs baseline: 1.8898x; 1.8898x over previous
#include <cuda_runtime.h>
#include <cuda_bf16.h>

// ---------------- problem constants ----------------
#define Bdim 2
#define Tdim 2048
#define Cdim 2048
#define Hn   16
#define HD   128
#define Mrows (Bdim * Tdim)   // 4096
#define Ncols (3 * Cdim)      // 6144
#define Kdim  Cdim            // 2048

// ---------------- device scratch (no runtime alloc allowed) ----------------
__device__ float g_xr [(size_t)Mrows * Kdim];    // tf32-rounded x       (~33.5 MB)
__device__ float g_wr [(size_t)Ncols * Kdim];    // tf32-rounded W_qkv   (~50 MB)
__device__ float g_qkv[(size_t)Mrows * Ncols];   // qkv (tf32-rounded)   (~100 MB)
__device__ int   g_idx [Mrows];
__device__ float g_top1[Mrows];
__device__ float g_ksh [Mrows * HD];             // tf32-rounded
__device__ float g_vsh [Mrows * HD];             // tf32-rounded

// ---------------- helpers ----------------
__device__ __forceinline__ unsigned f2tf(float x) {
    unsigned r;
    asm("cvt.rna.tf32.f32 %0, %1;" : "=r"(r) : "f"(x));
    return r;
}
__device__ __forceinline__ float rndtf(float x) { return __uint_as_float(f2tf(x)); }

__device__ __forceinline__ void mma_tf32(float* c, const unsigned* a, const unsigned* b) {
    asm volatile(
        "mma.sync.aligned.m16n8k8.row.col.f32.tf32.tf32.f32 "
        "{%0,%1,%2,%3}, {%4,%5,%6,%7}, {%8,%9}, {%0,%1,%2,%3};"
        : "+f"(c[0]), "+f"(c[1]), "+f"(c[2]), "+f"(c[3])
        : "r"(a[0]), "r"(a[1]), "r"(a[2]), "r"(a[3]), "r"(b[0]), "r"(b[1]));
}

__device__ __forceinline__ void cp16(unsigned* smem_dst, const float* gmem_src) {
    unsigned s = (unsigned)__cvta_generic_to_shared(smem_dst);
    asm volatile("cp.async.cg.shared.global [%0], [%1], 16;\n" :: "r"(s), "l"(gmem_src));
}
#define CP_COMMIT() asm volatile("cp.async.commit_group;\n" ::)
template <int N> __device__ __forceinline__ void cp_wait() {
    asm volatile("cp.async.wait_group %0;\n" :: "n"(N));
}

// ============================================================================
// Kernel 0: pre-round an fp32 array to tf32 (rna)
// ============================================================================
__global__ __launch_bounds__(256) void round_kernel(const float* __restrict__ src,
                                                    float* __restrict__ dst, int n4) {
    int i = blockIdx.x * 256 + threadIdx.x;
    if (i < n4) {
        float4 v = ((const float4*)src)[i];
        v.x = rndtf(v.x); v.y = rndtf(v.y); v.z = rndtf(v.z); v.w = rndtf(v.w);
        ((float4*)dst)[i] = v;
    }
}

// ============================================================================
// Kernel 1: gating logits (fp32 exact) -> argmax + top-1 softmax value
// ============================================================================
#define GATE_TOKS 8
__global__ __launch_bounds__(512) void gate_kernel(const float* __restrict__ x,
                                                   const float* __restrict__ Wg) {
    const int wid = threadIdx.x >> 5, lane = threadIdx.x & 31;
    __shared__ float sl[Hn];
    const float* wr = Wg + (size_t)wid * Cdim;
    const int m0 = blockIdx.x * GATE_TOKS;
    for (int tm = 0; tm < GATE_TOKS; tm++) {
        const int m = m0 + tm;
        const float* xr = x + (size_t)m * Cdim;
        float s = 0.f;
        #pragma unroll 8
        for (int k = lane; k < Cdim; k += 32) s += xr[k] * wr[k];
        #pragma unroll
        for (int o = 16; o; o >>= 1) s += __shfl_xor_sync(0xffffffffu, s, o);
        if (lane == 0) sl[wid] = s;
        __syncthreads();
        if (threadIdx.x == 0) {
            float mx = sl[0]; int bi = 0;
            #pragma unroll
            for (int h = 1; h < Hn; h++) { if (sl[h] > mx) { mx = sl[h]; bi = h; } }
            float den = 0.f;
            #pragma unroll
            for (int h = 0; h < Hn; h++) den += __expf(sl[h] - mx);
            g_idx[m]  = bi;
            g_top1[m] = 1.f / den;
        }
        __syncthreads();
    }
}

// ============================================================================
// Kernel 2: QKV GEMM, tf32 mma, cp.async 3-stage pipeline
// BM=128 BN=256 BK=32, 256 threads, 8 warps (2x4), warp tile 64x64.
// smem stage: A 128x36 + B 256x36 = 13824 words; 3 stages = 162 KB.
// ============================================================================
#define G_BM 128
#define G_BN 256
#define G_BK 32
#define G_STG 3
#define G_ASZ (G_BM * 36)            // 4608
#define G_STSZ (G_ASZ + G_BN * 36)   // 13824
#define G_SMEM_BYTES (G_STG * G_STSZ * 4)

__global__ __launch_bounds__(256, 1) void qkv_gemm() {
    extern __shared__ unsigned gsm[];
    const int tid = threadIdx.x;
    const int wid = tid >> 5, lane = tid & 31;
    const int grp = lane >> 2, qd = lane & 3;
    const int wm = (wid >> 2) * 64;     // 0 / 64
    const int wn = (wid & 3) * 64;      // 0..192
    const int m0 = blockIdx.y * G_BM, n0 = blockIdx.x * G_BN;

    const float* X = g_xr;
    const float* W = g_wr;

    float acc[4][8][4];
    #pragma unroll
    for (int mt = 0; mt < 4; mt++)
        #pragma unroll
        for (int nt = 0; nt < 8; nt++)
            #pragma unroll
            for (int r = 0; r < 4; r++) acc[mt][nt][r] = 0.f;

    // per-thread cp.async coords
    const int lr = tid >> 3;            // used as base row group
    const int lc = (tid & 7) << 2;      // col within 32

    // prologue: issue stages 0,1
    #pragma unroll
    for (int s = 0; s < 2; s++) {
        unsigned* As = gsm + s * G_STSZ;
        unsigned* Bs = As + G_ASZ;
        const int kt = s * G_BK;
        #pragma unroll
        for (int i = 0; i < 4; i++) {   // A: 128 rows
            int r = lr + i * 32;
            cp16(As + r * 36 + lc, X + (size_t)(m0 + r) * Kdim + kt + lc);
        }
        #pragma unroll
        for (int i = 0; i < 8; i++) {   // B: 256 rows
            int r = lr + i * 32;
            cp16(Bs + r * 36 + lc, W + (size_t)(n0 + r) * Kdim + kt + lc);
        }
        CP_COMMIT();
    }

    const int NIT = Kdim / G_BK;        // 64
    for (int it = 0; it < NIT; it++) {
        cp_wait<1>();
        __syncthreads();
        // prefetch stage it+2
        if (it + 2 < NIT) {
            int s = (it + 2) % G_STG;
            unsigned* As = gsm + s * G_STSZ;
            unsigned* Bs = As + G_ASZ;
            const int kt = (it + 2) * G_BK;
            #pragma unroll
            for (int i = 0; i < 4; i++) {
                int r = lr + i * 32;
                cp16(As + r * 36 + lc, X + (size_t)(m0 + r) * Kdim + kt + lc);
            }
            #pragma unroll
            for (int i = 0; i < 8; i++) {
                int r = lr + i * 32;
                cp16(Bs + r * 36 + lc, W + (size_t)(n0 + r) * Kdim + kt + lc);
            }
        }
        CP_COMMIT();

        const unsigned* As = gsm + (it % G_STG) * G_STSZ;
        const unsigned* Bs = As + G_ASZ;
        #pragma unroll
        for (int ks = 0; ks < G_BK; ks += 8) {
            unsigned a[4][4], b[8][2];
            #pragma unroll
            for (int mt = 0; mt < 4; mt++) {
                int rb = wm + mt * 16;
                a[mt][0] = As[(rb + grp) * 36 + ks + qd];
                a[mt][1] = As[(rb + grp + 8) * 36 + ks + qd];
                a[mt][2] = As[(rb + grp) * 36 + ks + qd + 4];
                a[mt][3] = As[(rb + grp + 8) * 36 + ks + qd + 4];
            }
            #pragma unroll
            for (int nt = 0; nt < 8; nt++) {
                int nb = wn + nt * 8;
                b[nt][0] = Bs[(nb + grp) * 36 + ks + qd];
                b[nt][1] = Bs[(nb + grp) * 36 + ks + qd + 4];
            }
            #pragma unroll
            for (int mt = 0; mt < 4; mt++)
                #pragma unroll
                for (int nt = 0; nt < 8; nt++)
                    mma_tf32(acc[mt][nt], a[mt], b[nt]);
        }
    }

    // epilogue: write tf32-ROUNDED qkv so downstream kernels can cp.async raw
    #pragma unroll
    for (int mt = 0; mt < 4; mt++) {
        int r0 = m0 + wm + mt * 16 + grp;
        #pragma unroll
        for (int nt = 0; nt < 8; nt++) {
            int cc = n0 + wn + nt * 8 + 2 * qd;
            *(float2*)(g_qkv + (size_t)r0 * Ncols + cc) =
                make_float2(rndtf(acc[mt][nt][0]), rndtf(acc[mt][nt][1]));
            *(float2*)(g_qkv + (size_t)(r0 + 8) * Ncols + cc) =
                make_float2(rndtf(acc[mt][nt][2]), rndtf(acc[mt][nt][3]));
        }
    }
}

// ============================================================================
// Kernel 3: select shared K/V head per token (writes tf32-rounded values)
// ============================================================================
__global__ __launch_bounds__(256) void select_kernel() {
    int i = blockIdx.x * 256 + threadIdx.x;
    int m = i >> 7, d = i & 127;
    int hsel = g_idx[m];
    const float* base = g_qkv + (size_t)m * Ncols;
    g_ksh[i] = base[Cdim + hsel * HD + d];                  // already rounded
    g_vsh[i] = rndtf(g_top1[m] * base[2 * Cdim + hsel * HD + d]);
}

// ============================================================================
// Kernel 4: causal flash attention, tf32 mma, cp.async double-buffered K/V,
// Q fragments hoisted to registers (Q smem region reused for P).
// BQ=128 (8 warps x 16 rows), BKV=64, hd=128.
// smem: Q/P 128*132 | K 2*64*132 | V 2*64*136  = 51200 words = 200 KB.
// ============================================================================
#define BQ   128
#define BKV  64
#define QST  132
#define KST  132
#define VST  136
#define PST  68
#define A_QWORDS (BQ * QST)                 // 16896 (>= 8 warps * 16 * PST = 8704)
#define A_KSTG   (BKV * KST)                // 8448
#define A_VSTG   (BKV * VST)                // 8704
#define A_SMEM_WORDS (A_QWORDS + 2 * A_KSTG + 2 * A_VSTG)
#define A_SMEM_BYTES (A_SMEM_WORDS * 4)

__global__ __launch_bounds__(256, 1) void attn_kernel(float* __restrict__ out) {
    extern __shared__ unsigned sm[];
    unsigned* Qs = sm;                       // later reused as P
    unsigned* Ks = sm + A_QWORDS;
    unsigned* Vs = Ks + 2 * A_KSTG;

    const int qt = gridDim.x - 1 - blockIdx.x;  // heavy tiles first
    const int bh = blockIdx.y;
    const int b = bh >> 4, h = bh & 15;
    const int qbase = qt * BQ;
    const int tid = threadIdx.x, wid = tid >> 5, lane = tid & 31;
    const int grp = lane >> 2, qd = lane & 3;

    const float* qg = g_qkv + (size_t)(b * Tdim + qbase) * Ncols + h * HD;
    const float* kg = g_ksh + (size_t)b * Tdim * HD;
    const float* vg = g_vsh + (size_t)b * Tdim * HD;

    const int cr = tid >> 5;                 // 0..7  (row group for K/V cp)
    const int ccol = (tid & 31) << 2;        // 0..124

    // prologue: Q tile + KV tile 0, one commit group
    #pragma unroll
    for (int i = 0; i < 16; i++) {
        int r = cr + i * 8;                  // 0..127
        cp16(Qs + r * QST + ccol, qg + (size_t)r * Ncols + ccol);
    }
    #pragma unroll
    for (int i = 0; i < 8; i++) {
        int r = cr + i * 8;                  // 0..63
        cp16(Ks + r * KST + ccol, kg + (size_t)r * HD + ccol);
        cp16(Vs + r * VST + ccol, vg + (size_t)r * HD + ccol);
    }
    CP_COMMIT();
    cp_wait<0>();
    __syncthreads();

    // hoist Q fragments into registers
    unsigned qf[16][4];
    {
        const unsigned* qb = Qs + (wid * 16) * QST;
        #pragma unroll
        for (int kk = 0; kk < 16; kk++) {
            qf[kk][0] = qb[grp * QST + kk * 8 + qd];
            qf[kk][1] = qb[(grp + 8) * QST + kk * 8 + qd];
            qf[kk][2] = qb[grp * QST + kk * 8 + qd + 4];
            qf[kk][3] = qb[(grp + 8) * QST + kk * 8 + qd + 4];
        }
    }
    __syncthreads();                          // Qs now reusable as P

    float o[16][4];
    #pragma unroll
    for (int n = 0; n < 16; n++)
        #pragma unroll
        for (int r = 0; r < 4; r++) o[n][r] = 0.f;
    float mi0 = -1e30f, mi1 = -1e30f, li0 = 0.f, li1 = 0.f;

    const int qrow_last = qbase + wid * 16 + 15;
    const int ntiles = (qbase + BQ) / BKV;
    const float sc = 0.08838834764831845f;    // 1/sqrt(128)
    unsigned* pw = Qs + wid * 16 * PST;       // per-warp P region (overlays Qs)

    for (int t = 0; t < ntiles; t++) {
        const int kstart = t * BKV;
        cp_wait<0>();
        __syncthreads();                      // KV(t) visible; KV(t-1) readers done
        // prefetch KV(t+1) into the other stage
        if (t + 1 < ntiles) {
            const int st = (t + 1) & 1;
            const int ks2 = (t + 1) * BKV;
            unsigned* kd = Ks + st * A_KSTG;
            unsigned* vd = Vs + st * A_VSTG;
            #pragma unroll
            for (int i = 0; i < 8; i++) {
                int r = cr + i * 8;
                cp16(kd + r * KST + ccol, kg + (size_t)(ks2 + r) * HD + ccol);
                cp16(vd + r * VST + ccol, vg + (size_t)(ks2 + r) * HD + ccol);
            }
        }
        CP_COMMIT();

        if (kstart <= qrow_last) {
            const unsigned* Kc = Ks + (t & 1) * A_KSTG;
            const unsigned* Vc = Vs + (t & 1) * A_VSTG;

            float s[8][4];
            #pragma unroll
            for (int n = 0; n < 8; n++)
                #pragma unroll
                for (int r = 0; r < 4; r++) s[n][r] = 0.f;

            // S = Q @ K^T
            #pragma unroll
            for (int kk = 0; kk < 16; kk++) {
                #pragma unroll
                for (int nt = 0; nt < 8; nt++) {
                    unsigned bb[2];
                    bb[0] = Kc[(nt * 8 + grp) * KST + kk * 8 + qd];
                    bb[1] = Kc[(nt * 8 + grp) * KST + kk * 8 + qd + 4];
                    mma_tf32(s[nt], qf[kk], bb);
                }
            }

            // scale + causal mask
            const int row0 = qbase + wid * 16 + grp;
            const int row1 = row0 + 8;
            #pragma unroll
            for (int nt = 0; nt < 8; nt++) {
                int cbase = kstart + nt * 8 + 2 * qd;
                s[nt][0] = (cbase     <= row0) ? s[nt][0] * sc : -1e30f;
                s[nt][1] = (cbase + 1 <= row0) ? s[nt][1] * sc : -1e30f;
                s[nt][2] = (cbase     <= row1) ? s[nt][2] * sc : -1e30f;
                s[nt][3] = (cbase + 1 <= row1) ? s[nt][3] * sc : -1e30f;
            }

            // online softmax
            float rm0 = -1e30f, rm1 = -1e30f;
            #pragma unroll
            for (int nt = 0; nt < 8; nt++) {
                rm0 = fmaxf(rm0, fmaxf(s[nt][0], s[nt][1]));
                rm1 = fmaxf(rm1, fmaxf(s[nt][2], s[nt][3]));
            }
            #pragma unroll
            for (int off = 1; off < 4; off <<= 1) {
                rm0 = fmaxf(rm0, __shfl_xor_sync(0xffffffffu, rm0, off));
                rm1 = fmaxf(rm1, __shfl_xor_sync(0xffffffffu, rm1, off));
            }
            const float mn0 = fmaxf(mi0, rm0), mn1 = fmaxf(mi1, rm1);
            const float f0 = __expf(mi0 - mn0), f1 = __expf(mi1 - mn1);
            mi0 = mn0; mi1 = mn1;

            float ls0 = 0.f, ls1 = 0.f;
            #pragma unroll
            for (int nt = 0; nt < 8; nt++) {
                float p0 = __expf(s[nt][0] - mn0), p1 = __expf(s[nt][1] - mn0);
                float p2 = __expf(s[nt][2] - mn1), p3 = __expf(s[nt][3] - mn1);
                ls0 += p0 + p1; ls1 += p2 + p3;
                int c = nt * 8 + 2 * qd;
                pw[grp * PST + c]           = f2tf(p0);
                pw[grp * PST + c + 1]       = f2tf(p1);
                pw[(grp + 8) * PST + c]     = f2tf(p2);
                pw[(grp + 8) * PST + c + 1] = f2tf(p3);
            }
            #pragma unroll
            for (int off = 1; off < 4; off <<= 1) {
                ls0 += __shfl_xor_sync(0xffffffffu, ls0, off);
                ls1 += __shfl_xor_sync(0xffffffffu, ls1, off);
            }
            li0 = li0 * f0 + ls0;
            li1 = li1 * f1 + ls1;
            #pragma unroll
            for (int nt = 0; nt < 16; nt++) {
                o[nt][0] *= f0; o[nt][1] *= f0;
                o[nt][2] *= f1; o[nt][3] *= f1;
            }
            __syncwarp();

            // O += P @ V
            #pragma unroll
            for (int kk = 0; kk < 8; kk++) {
                unsigned a[4];
                a[0] = pw[grp * PST + kk * 8 + qd];
                a[1] = pw[(grp + 8) * PST + kk * 8 + qd];
                a[2] = pw[grp * PST + kk * 8 + qd + 4];
                a[3] = pw[(grp + 8) * PST + kk * 8 + qd + 4];
                #pragma unroll
                for (int nt = 0; nt < 16; nt++) {
                    unsigned bb[2];
                    bb[0] = Vc[(kk * 8 + qd) * VST + nt * 8 + grp];
                    bb[1] = Vc[(kk * 8 + qd + 4) * VST + nt * 8 + grp];
                    mma_tf32(o[nt], a, bb);
                }
            }
        }
    }

    // normalize + write: out[b, t, h*HD + d]
    const float inv0 = 1.f / li0, inv1 = 1.f / li1;
    const size_t r0 = (size_t)(b * Tdim + qbase + wid * 16 + grp) * Cdim;
    const size_t r1 = r0 + (size_t)8 * Cdim;
    #pragma unroll
    for (int nt = 0; nt < 16; nt++) {
        int c = h * HD + nt * 8 + 2 * qd;
        *(float2*)(out + r0 + c) = make_float2(o[nt][0] * inv0, o[nt][1] * inv0);
        *(float2*)(out + r1 + c) = make_float2(o[nt][2] * inv1, o[nt][3] * inv1);
    }
}

// ============================================================================
// host launcher
// ============================================================================
extern "C" void kernel_launch(void* const* d_in, const int* in_sizes, int n_in,
                              void* d_out, int out_size) {
    const float* x    = (const float*)d_in[0];
    const float* Wg   = (const float*)d_in[1];
    const float* Wqkv = (const float*)d_in[2];
    float* out = (float*)d_out;

    static int attr_set = 0;
    if (!attr_set) {
        cudaFuncSetAttribute(qkv_gemm, cudaFuncAttributeMaxDynamicSharedMemorySize, G_SMEM_BYTES);
        cudaFuncSetAttribute(attn_kernel, cudaFuncAttributeMaxDynamicSharedMemorySize, A_SMEM_BYTES);
        attr_set = 1;
    }

    // pre-round x and W_qkv to tf32
    {
        float* xr; cudaGetSymbolAddress((void**)&xr, g_xr);
        float* wr; cudaGetSymbolAddress((void**)&wr, g_wr);
        int nx4 = Mrows * Kdim / 4;
        int nw4 = Ncols * Kdim / 4;
        round_kernel<<<(nx4 + 255) / 256, 256>>>(x, xr, nx4);
        round_kernel<<<(nw4 + 255) / 256, 256>>>(Wqkv, wr, nw4);
    }

    gate_kernel<<<Mrows / GATE_TOKS, 512>>>(x, Wg);

    dim3 gg(Ncols / G_BN, Mrows / G_BM);     // 24 x 32
    qkv_gemm<<<gg, 256, G_SMEM_BYTES>>>();

    select_kernel<<<(Mrows * HD) / 256, 256>>>();

    dim3 ga(Tdim / BQ, Bdim * Hn);           // 16 x 32
    attn_kernel<<<ga, 256, A_SMEM_BYTES>>>(out);
}

// round 9
// speedup vs baseline: 1.9539x; 1.0339x over previous
#include <cuda_runtime.h>
#include <cuda_bf16.h>
#include <cstdint>

// ---------------- problem constants ----------------
#define Bdim 2
#define Tdim 2048
#define Cdim 2048
#define Hn   16
#define HD   128
#define Mrows (Bdim * Tdim)   // 4096
#define Ncols (3 * Cdim)      // 6144
#define Kdim  Cdim            // 2048

// ---------------- device scratch (no runtime alloc allowed) ----------------
__device__ float g_xr [(size_t)Mrows * Kdim];    // tf32-rounded x
__device__ float g_wr [(size_t)Ncols * Kdim];    // tf32-rounded W_qkv
__device__ float g_qkv[(size_t)Mrows * Ncols];   // qkv (tf32-rounded)
__device__ int   g_idx [Mrows];
__device__ float g_top1[Mrows];
__device__ float g_ksh [Mrows * HD];             // tf32-rounded
__device__ float g_vsh [Mrows * HD];             // tf32-rounded

// ---------------- helpers ----------------
__device__ __forceinline__ unsigned f2tf(float x) {
    unsigned r;
    asm("cvt.rna.tf32.f32 %0, %1;" : "=r"(r) : "f"(x));
    return r;
}
__device__ __forceinline__ float rndtf(float x) { return __uint_as_float(f2tf(x)); }

__device__ __forceinline__ void mma_tf32(float* c, const unsigned* a, const unsigned* b) {
    asm volatile(
        "mma.sync.aligned.m16n8k8.row.col.f32.tf32.tf32.f32 "
        "{%0,%1,%2,%3}, {%4,%5,%6,%7}, {%8,%9}, {%0,%1,%2,%3};"
        : "+f"(c[0]), "+f"(c[1]), "+f"(c[2]), "+f"(c[3])
        : "r"(a[0]), "r"(a[1]), "r"(a[2]), "r"(a[3]), "r"(b[0]), "r"(b[1]));
}

__device__ __forceinline__ void cp16(unsigned* smem_dst, const float* gmem_src) {
    unsigned s = (unsigned)__cvta_generic_to_shared(smem_dst);
    asm volatile("cp.async.cg.shared.global [%0], [%1], 16;\n" :: "r"(s), "l"(gmem_src));
}
#define CP_COMMIT() asm volatile("cp.async.commit_group;\n" ::)
template <int N> __device__ __forceinline__ void cp_wait() {
    asm volatile("cp.async.wait_group %0;\n" :: "n"(N));
}

// ============================================================================
// Kernel 0: pre-round an fp32 array to tf32 (rna)
// ============================================================================
__global__ __launch_bounds__(256) void round_kernel(const float* __restrict__ src,
                                                    float* __restrict__ dst, int n4) {
    int i = blockIdx.x * 256 + threadIdx.x;
    if (i < n4) {
        float4 v = ((const float4*)src)[i];
        v.x = rndtf(v.x); v.y = rndtf(v.y); v.z = rndtf(v.z); v.w = rndtf(v.w);
        ((float4*)dst)[i] = v;
    }
}

// ============================================================================
// Kernel 1: gating logits (fp32 exact) -> argmax + top-1 softmax value
// ============================================================================
#define GATE_TOKS 8
__global__ __launch_bounds__(512) void gate_kernel(const float* __restrict__ x,
                                                   const float* __restrict__ Wg) {
    const int wid = threadIdx.x >> 5, lane = threadIdx.x & 31;
    __shared__ float sl[Hn];
    const float* wr = Wg + (size_t)wid * Cdim;
    const int m0 = blockIdx.x * GATE_TOKS;
    for (int tm = 0; tm < GATE_TOKS; tm++) {
        const int m = m0 + tm;
        const float* xr = x + (size_t)m * Cdim;
        float s = 0.f;
        #pragma unroll 8
        for (int k = lane; k < Cdim; k += 32) s += xr[k] * wr[k];
        #pragma unroll
        for (int o = 16; o; o >>= 1) s += __shfl_xor_sync(0xffffffffu, s, o);
        if (lane == 0) sl[wid] = s;
        __syncthreads();
        if (threadIdx.x == 0) {
            float mx = sl[0]; int bi = 0;
            #pragma unroll
            for (int h = 1; h < Hn; h++) { if (sl[h] > mx) { mx = sl[h]; bi = h; } }
            float den = 0.f;
            #pragma unroll
            for (int h = 0; h < Hn; h++) den += __expf(sl[h] - mx);
            g_idx[m]  = bi;
            g_top1[m] = 1.f / den;
        }
        __syncthreads();
    }
}

// ============================================================================
// Kernel 2: QKV GEMM, tf32 mma.sync, cp.async 3-stage pipeline, 2 CTAs/SM
// BM=128 BN=128 BK=32, 256 threads, 8 warps (2x4), warp tile 64x32.
// smem stage: A 128x36 + B 128x36 = 9216 words; 3 stages = 108 KB.
// ============================================================================
#define G_BM 128
#define G_BN 128
#define G_BK 32
#define G_STG 3
#define G_ASZ (G_BM * 36)            // 4608
#define G_STSZ (2 * G_ASZ)           // 9216 words
#define G_SMEM_BYTES (G_STG * G_STSZ * 4)

__global__ __launch_bounds__(256, 2) void qkv_gemm() {
    extern __shared__ unsigned gsm[];
    const int tid = threadIdx.x;
    const int wid = tid >> 5, lane = tid & 31;
    const int grp = lane >> 2, qd = lane & 3;
    const int wm = (wid >> 2) * 64;     // 0 / 64
    const int wn = (wid & 3) * 32;      // 0..96
    const int m0 = blockIdx.y * G_BM, n0 = blockIdx.x * G_BN;

    const float* X = g_xr;
    const float* W = g_wr;

    float acc[4][4][4];
    #pragma unroll
    for (int mt = 0; mt < 4; mt++)
        #pragma unroll
        for (int nt = 0; nt < 4; nt++)
            #pragma unroll
            for (int r = 0; r < 4; r++) acc[mt][nt][r] = 0.f;

    // per-thread cp.async coords: 256 thr cover 32 rows x 8 chunks per pass
    const int lr = tid >> 3;            // 0..31
    const int lc = (tid & 7) << 2;      // 0,4,...,28

    // prologue: issue stages 0,1
    #pragma unroll
    for (int s = 0; s < 2; s++) {
        unsigned* As = gsm + s * G_STSZ;
        unsigned* Bs = As + G_ASZ;
        const int kt = s * G_BK;
        #pragma unroll
        for (int i = 0; i < 4; i++) {
            int r = lr + i * 32;
            cp16(As + r * 36 + lc, X + (size_t)(m0 + r) * Kdim + kt + lc);
            cp16(Bs + r * 36 + lc, W + (size_t)(n0 + r) * Kdim + kt + lc);
        }
        CP_COMMIT();
    }

    const int NIT = Kdim / G_BK;        // 64
    for (int it = 0; it < NIT; it++) {
        cp_wait<1>();
        __syncthreads();
        // prefetch stage it+2
        if (it + 2 < NIT) {
            int s = (it + 2) % G_STG;
            unsigned* As = gsm + s * G_STSZ;
            unsigned* Bs = As + G_ASZ;
            const int kt = (it + 2) * G_BK;
            #pragma unroll
            for (int i = 0; i < 4; i++) {
                int r = lr + i * 32;
                cp16(As + r * 36 + lc, X + (size_t)(m0 + r) * Kdim + kt + lc);
                cp16(Bs + r * 36 + lc, W + (size_t)(n0 + r) * Kdim + kt + lc);
            }
        }
        CP_COMMIT();

        const unsigned* As = gsm + (it % G_STG) * G_STSZ;
        const unsigned* Bs = As + G_ASZ;
        #pragma unroll
        for (int ks = 0; ks < G_BK; ks += 8) {
            unsigned a[4][4], b[4][2];
            #pragma unroll
            for (int mt = 0; mt < 4; mt++) {
                int rb = wm + mt * 16;
                a[mt][0] = As[(rb + grp) * 36 + ks + qd];
                a[mt][1] = As[(rb + grp + 8) * 36 + ks + qd];
                a[mt][2] = As[(rb + grp) * 36 + ks + qd + 4];
                a[mt][3] = As[(rb + grp + 8) * 36 + ks + qd + 4];
            }
            #pragma unroll
            for (int nt = 0; nt < 4; nt++) {
                int nb = wn + nt * 8;
                b[nt][0] = Bs[(nb + grp) * 36 + ks + qd];
                b[nt][1] = Bs[(nb + grp) * 36 + ks + qd + 4];
            }
            #pragma unroll
            for (int mt = 0; mt < 4; mt++)
                #pragma unroll
                for (int nt = 0; nt < 4; nt++)
                    mma_tf32(acc[mt][nt], a[mt], b[nt]);
        }
    }

    // epilogue: write tf32-ROUNDED qkv
    #pragma unroll
    for (int mt = 0; mt < 4; mt++) {
        int r0 = m0 + wm + mt * 16 + grp;
        #pragma unroll
        for (int nt = 0; nt < 4; nt++) {
            int cc = n0 + wn + nt * 8 + 2 * qd;
            *(float2*)(g_qkv + (size_t)r0 * Ncols + cc) =
                make_float2(rndtf(acc[mt][nt][0]), rndtf(acc[mt][nt][1]));
            *(float2*)(g_qkv + (size_t)(r0 + 8) * Ncols + cc) =
                make_float2(rndtf(acc[mt][nt][2]), rndtf(acc[mt][nt][3]));
        }
    }
}

// ============================================================================
// Kernel 3: select shared K/V head per token (writes tf32-rounded values)
// ============================================================================
__global__ __launch_bounds__(256) void select_kernel() {
    int i = blockIdx.x * 256 + threadIdx.x;
    int m = i >> 7, d = i & 127;
    int hsel = g_idx[m];
    const float* base = g_qkv + (size_t)m * Ncols;
    g_ksh[i] = base[Cdim + hsel * HD + d];
    g_vsh[i] = rndtf(g_top1[m] * base[2 * Cdim + hsel * HD + d]);
}

// ============================================================================
// Kernel 4: causal flash attention, tf32 mma.sync, cp.async double-buffered K/V,
// Q fragments hoisted to registers (Q smem region reused for P).  (R2-proven)
// ============================================================================
#define BQ   128
#define BKV  64
#define QST  132
#define KST  132
#define VST  136
#define PST  68
#define A_QWORDS (BQ * QST)
#define A_KSTG   (BKV * KST)
#define A_VSTG   (BKV * VST)
#define A_SMEM_WORDS (A_QWORDS + 2 * A_KSTG + 2 * A_VSTG)
#define A_SMEM_BYTES (A_SMEM_WORDS * 4)

__global__ __launch_bounds__(256, 1) void attn_kernel(float* __restrict__ out) {
    extern __shared__ unsigned sm[];
    unsigned* Qs = sm;
    unsigned* Ks = sm + A_QWORDS;
    unsigned* Vs = Ks + 2 * A_KSTG;

    const int qt = gridDim.x - 1 - blockIdx.x;
    const int bh = blockIdx.y;
    const int b = bh >> 4, h = bh & 15;
    const int qbase = qt * BQ;
    const int tid = threadIdx.x, wid = tid >> 5, lane = tid & 31;
    const int grp = lane >> 2, qd = lane & 3;

    const float* qg = g_qkv + (size_t)(b * Tdim + qbase) * Ncols + h * HD;
    const float* kg = g_ksh + (size_t)b * Tdim * HD;
    const float* vg = g_vsh + (size_t)b * Tdim * HD;

    const int cr = tid >> 5;
    const int ccol = (tid & 31) << 2;

    #pragma unroll
    for (int i = 0; i < 16; i++) {
        int r = cr + i * 8;
        cp16(Qs + r * QST + ccol, qg + (size_t)r * Ncols + ccol);
    }
    #pragma unroll
    for (int i = 0; i < 8; i++) {
        int r = cr + i * 8;
        cp16(Ks + r * KST + ccol, kg + (size_t)r * HD + ccol);
        cp16(Vs + r * VST + ccol, vg + (size_t)r * HD + ccol);
    }
    CP_COMMIT();
    cp_wait<0>();
    __syncthreads();

    unsigned qf[16][4];
    {
        const unsigned* qb = Qs + (wid * 16) * QST;
        #pragma unroll
        for (int kk = 0; kk < 16; kk++) {
            qf[kk][0] = qb[grp * QST + kk * 8 + qd];
            qf[kk][1] = qb[(grp + 8) * QST + kk * 8 + qd];
            qf[kk][2] = qb[grp * QST + kk * 8 + qd + 4];
            qf[kk][3] = qb[(grp + 8) * QST + kk * 8 + qd + 4];
        }
    }
    __syncthreads();

    float o[16][4];
    #pragma unroll
    for (int n = 0; n < 16; n++)
        #pragma unroll
        for (int r = 0; r < 4; r++) o[n][r] = 0.f;
    float mi0 = -1e30f, mi1 = -1e30f, li0 = 0.f, li1 = 0.f;

    const int qrow_last = qbase + wid * 16 + 15;
    const int ntiles = (qbase + BQ) / BKV;
    const float sc = 0.08838834764831845f;
    unsigned* pw = Qs + wid * 16 * PST;

    for (int t = 0; t < ntiles; t++) {
        const int kstart = t * BKV;
        cp_wait<0>();
        __syncthreads();
        if (t + 1 < ntiles) {
            const int st = (t + 1) & 1;
            const int ks2 = (t + 1) * BKV;
            unsigned* kd = Ks + st * A_KSTG;
            unsigned* vd = Vs + st * A_VSTG;
            #pragma unroll
            for (int i = 0; i < 8; i++) {
                int r = cr + i * 8;
                cp16(kd + r * KST + ccol, kg + (size_t)(ks2 + r) * HD + ccol);
                cp16(vd + r * VST + ccol, vg + (size_t)(ks2 + r) * HD + ccol);
            }
        }
        CP_COMMIT();

        if (kstart <= qrow_last) {
            const unsigned* Kc = Ks + (t & 1) * A_KSTG;
            const unsigned* Vc = Vs + (t & 1) * A_VSTG;

            float s[8][4];
            #pragma unroll
            for (int n = 0; n < 8; n++)
                #pragma unroll
                for (int r = 0; r < 4; r++) s[n][r] = 0.f;

            #pragma unroll
            for (int kk = 0; kk < 16; kk++) {
                #pragma unroll
                for (int nt = 0; nt < 8; nt++) {
                    unsigned bb[2];
                    bb[0] = Kc[(nt * 8 + grp) * KST + kk * 8 + qd];
                    bb[1] = Kc[(nt * 8 + grp) * KST + kk * 8 + qd + 4];
                    mma_tf32(s[nt], qf[kk], bb);
                }
            }

            const int row0 = qbase + wid * 16 + grp;
            const int row1 = row0 + 8;
            #pragma unroll
            for (int nt = 0; nt < 8; nt++) {
                int cbase = kstart + nt * 8 + 2 * qd;
                s[nt][0] = (cbase     <= row0) ? s[nt][0] * sc : -1e30f;
                s[nt][1] = (cbase + 1 <= row0) ? s[nt][1] * sc : -1e30f;
                s[nt][2] = (cbase     <= row1) ? s[nt][2] * sc : -1e30f;
                s[nt][3] = (cbase + 1 <= row1) ? s[nt][3] * sc : -1e30f;
            }

            float rm0 = -1e30f, rm1 = -1e30f;
            #pragma unroll
            for (int nt = 0; nt < 8; nt++) {
                rm0 = fmaxf(rm0, fmaxf(s[nt][0], s[nt][1]));
                rm1 = fmaxf(rm1, fmaxf(s[nt][2], s[nt][3]));
            }
            #pragma unroll
            for (int off = 1; off < 4; off <<= 1) {
                rm0 = fmaxf(rm0, __shfl_xor_sync(0xffffffffu, rm0, off));
                rm1 = fmaxf(rm1, __shfl_xor_sync(0xffffffffu, rm1, off));
            }
            const float mn0 = fmaxf(mi0, rm0), mn1 = fmaxf(mi1, rm1);
            const float f0 = __expf(mi0 - mn0), f1 = __expf(mi1 - mn1);
            mi0 = mn0; mi1 = mn1;

            float ls0 = 0.f, ls1 = 0.f;
            #pragma unroll
            for (int nt = 0; nt < 8; nt++) {
                float p0 = __expf(s[nt][0] - mn0), p1 = __expf(s[nt][1] - mn0);
                float p2 = __expf(s[nt][2] - mn1), p3 = __expf(s[nt][3] - mn1);
                ls0 += p0 + p1; ls1 += p2 + p3;
                int c = nt * 8 + 2 * qd;
                pw[grp * PST + c]           = f2tf(p0);
                pw[grp * PST + c + 1]       = f2tf(p1);
                pw[(grp + 8) * PST + c]     = f2tf(p2);
                pw[(grp + 8) * PST + c + 1] = f2tf(p3);
            }
            #pragma unroll
            for (int off = 1; off < 4; off <<= 1) {
                ls0 += __shfl_xor_sync(0xffffffffu, ls0, off);
                ls1 += __shfl_xor_sync(0xffffffffu, ls1, off);
            }
            li0 = li0 * f0 + ls0;
            li1 = li1 * f1 + ls1;
            #pragma unroll
            for (int nt = 0; nt < 16; nt++) {
                o[nt][0] *= f0; o[nt][1] *= f0;
                o[nt][2] *= f1; o[nt][3] *= f1;
            }
            __syncwarp();

            #pragma unroll
            for (int kk = 0; kk < 8; kk++) {
                unsigned a[4];
                a[0] = pw[grp * PST + kk * 8 + qd];
                a[1] = pw[(grp + 8) * PST + kk * 8 + qd];
                a[2] = pw[grp * PST + kk * 8 + qd + 4];
                a[3] = pw[(grp + 8) * PST + kk * 8 + qd + 4];
                #pragma unroll
                for (int nt = 0; nt < 16; nt++) {
                    unsigned bb[2];
                    bb[0] = Vc[(kk * 8 + qd) * VST + nt * 8 + grp];
                    bb[1] = Vc[(kk * 8 + qd + 4) * VST + nt * 8 + grp];
                    mma_tf32(o[nt], a, bb);
                }
            }
        }
    }

    const float inv0 = 1.f / li0, inv1 = 1.f / li1;
    const size_t r0 = (size_t)(b * Tdim + qbase + wid * 16 + grp) * Cdim;
    const size_t r1 = r0 + (size_t)8 * Cdim;
    #pragma unroll
    for (int nt = 0; nt < 16; nt++) {
        int c = h * HD + nt * 8 + 2 * qd;
        *(float2*)(out + r0 + c) = make_float2(o[nt][0] * inv0, o[nt][1] * inv0);
        *(float2*)(out + r1 + c) = make_float2(o[nt][2] * inv1, o[nt][3] * inv1);
    }
}

// ============================================================================
// host launcher
// ============================================================================
extern "C" void kernel_launch(void* const* d_in, const int* in_sizes, int n_in,
                              void* d_out, int out_size) {
    const float* x    = (const float*)d_in[0];
    const float* Wg   = (const float*)d_in[1];
    const float* Wqkv = (const float*)d_in[2];
    float* out = (float*)d_out;

    static int attr_set = 0;
    if (!attr_set) {
        cudaFuncSetAttribute(qkv_gemm, cudaFuncAttributeMaxDynamicSharedMemorySize, G_SMEM_BYTES);
        cudaFuncSetAttribute(attn_kernel, cudaFuncAttributeMaxDynamicSharedMemorySize, A_SMEM_BYTES);
        attr_set = 1;
    }

    // pre-round x and W_qkv to tf32
    {
        float* xr; cudaGetSymbolAddress((void**)&xr, g_xr);
        float* wr; cudaGetSymbolAddress((void**)&wr, g_wr);
        int nx4 = Mrows * Kdim / 4;
        int nw4 = Ncols * Kdim / 4;
        round_kernel<<<(nx4 + 255) / 256, 256>>>(x, xr, nx4);
        round_kernel<<<(nw4 + 255) / 256, 256>>>(Wqkv, wr, nw4);
    }

    gate_kernel<<<Mrows / GATE_TOKS, 512>>>(x, Wg);

    dim3 gg(Ncols / G_BN, Mrows / G_BM);     // 48 x 32
    qkv_gemm<<<gg, 256, G_SMEM_BYTES>>>();

    select_kernel<<<(Mrows * HD) / 256, 256>>>();

    dim3 ga(Tdim / BQ, Bdim * Hn);           // 16 x 32
    attn_kernel<<<ga, 256, A_SMEM_BYTES>>>(out);
}

// round 10
// speedup vs baseline: 3.1628x; 1.6187x over previous
#include <cuda_runtime.h>
#include <cuda_bf16.h>
#include <cstdint>

// ---------------- problem constants ----------------
#define Bdim 2
#define Tdim 2048
#define Cdim 2048
#define Hn   16
#define HD   128
#define Mrows (Bdim * Tdim)   // 4096
#define Ncols (3 * Cdim)      // 6144
#define Kdim  Cdim            // 2048

// ---------------- device scratch (no runtime alloc allowed) ----------------
__device__ float g_xr [(size_t)Mrows * Kdim];    // tf32-rounded x
__device__ float g_wr [(size_t)Ncols * Kdim];    // tf32-rounded W_qkv
__device__ float g_q  [(size_t)Mrows * Cdim];    // Q only (tf32-rounded)
__device__ int   g_idx [Mrows];
__device__ float g_top1[Mrows];
__device__ int   g_cnt [Hn];
__device__ int   g_list[Hn * Mrows];
__device__ float g_ksh [Mrows * HD];             // tf32-rounded
__device__ float g_vsh [Mrows * HD];             // tf32-rounded

// ---------------- helpers ----------------
__device__ __forceinline__ unsigned f2tf(float x) {
    unsigned r;
    asm("cvt.rna.tf32.f32 %0, %1;" : "=r"(r) : "f"(x));
    return r;
}
__device__ __forceinline__ float rndtf(float x) { return __uint_as_float(f2tf(x)); }

__device__ __forceinline__ void mma_tf32(float* c, const unsigned* a, const unsigned* b) {
    asm volatile(
        "mma.sync.aligned.m16n8k8.row.col.f32.tf32.tf32.f32 "
        "{%0,%1,%2,%3}, {%4,%5,%6,%7}, {%8,%9}, {%0,%1,%2,%3};"
        : "+f"(c[0]), "+f"(c[1]), "+f"(c[2]), "+f"(c[3])
        : "r"(a[0]), "r"(a[1]), "r"(a[2]), "r"(a[3]), "r"(b[0]), "r"(b[1]));
}

__device__ __forceinline__ void cp16(unsigned* smem_dst, const float* gmem_src) {
    unsigned s = (unsigned)__cvta_generic_to_shared(smem_dst);
    asm volatile("cp.async.cg.shared.global [%0], [%1], 16;\n" :: "r"(s), "l"(gmem_src));
}
#define CP_COMMIT() asm volatile("cp.async.commit_group;\n" ::)
template <int N> __device__ __forceinline__ void cp_wait() {
    asm volatile("cp.async.wait_group %0;\n" :: "n"(N));
}

// ============================================================================
// Kernel 0: pre-round an fp32 array to tf32 (rna)
// ============================================================================
__global__ __launch_bounds__(256) void round_kernel(const float* __restrict__ src,
                                                    float* __restrict__ dst, int n4) {
    int i = blockIdx.x * 256 + threadIdx.x;
    if (i < n4) {
        float4 v = ((const float4*)src)[i];
        v.x = rndtf(v.x); v.y = rndtf(v.y); v.z = rndtf(v.z); v.w = rndtf(v.w);
        ((float4*)dst)[i] = v;
    }
}

// ============================================================================
// Kernel 1: gating logits (fp32 exact) -> argmax + top-1 softmax value
// ============================================================================
#define GATE_TOKS 8
__global__ __launch_bounds__(512) void gate_kernel(const float* __restrict__ x,
                                                   const float* __restrict__ Wg) {
    const int wid = threadIdx.x >> 5, lane = threadIdx.x & 31;
    __shared__ float sl[Hn];
    const float* wr = Wg + (size_t)wid * Cdim;
    const int m0 = blockIdx.x * GATE_TOKS;
    for (int tm = 0; tm < GATE_TOKS; tm++) {
        const int m = m0 + tm;
        const float* xr = x + (size_t)m * Cdim;
        float s = 0.f;
        #pragma unroll 8
        for (int k = lane; k < Cdim; k += 32) s += xr[k] * wr[k];
        #pragma unroll
        for (int o = 16; o; o >>= 1) s += __shfl_xor_sync(0xffffffffu, s, o);
        if (lane == 0) sl[wid] = s;
        __syncthreads();
        if (threadIdx.x == 0) {
            float mx = sl[0]; int bi = 0;
            #pragma unroll
            for (int h = 1; h < Hn; h++) { if (sl[h] > mx) { mx = sl[h]; bi = h; } }
            float den = 0.f;
            #pragma unroll
            for (int h = 0; h < Hn; h++) den += __expf(sl[h] - mx);
            g_idx[m]  = bi;
            g_top1[m] = 1.f / den;
        }
        __syncthreads();
    }
}

// ============================================================================
// Kernel 1b: group tokens by selected head
// ============================================================================
__global__ void zero_cnt_kernel() {
    if (threadIdx.x < Hn) g_cnt[threadIdx.x] = 0;
}
__global__ __launch_bounds__(256) void build_groups_kernel() {
    int m = blockIdx.x * 256 + threadIdx.x;
    int h = g_idx[m];
    int pos = atomicAdd(&g_cnt[h], 1);
    g_list[h * Mrows + pos] = m;   // order nondeterministic; per-token result isn't
}

// ============================================================================
// Kernel 2: fused GEMM (tf32 mma.sync, cp.async 3-stage, 2 CTAs/SM)
//   blockIdx.x in [0,16):  Q tiles   -> g_q   (all tokens, 2048 cols)
//   blockIdx.x in [16,48): KV tiles  -> g_ksh / g_vsh (gathered token rows,
//                          head h = (x-16)>>1, which = (x-16)&1: 0=K, 1=V)
// BM=128 BN=128 BK=32, 256 threads, warp tile 64x32.
// ============================================================================
#define G_BM 128
#define G_BN 128
#define G_BK 32
#define G_STG 3
#define G_ASZ (G_BM * 36)            // 4608
#define G_STSZ (2 * G_ASZ)           // 9216 words
#define G_SMEM_BYTES (G_STG * G_STSZ * 4)

__global__ __launch_bounds__(256, 2) void fused_gemm() {
    extern __shared__ unsigned gsm[];
    const int tid = threadIdx.x;
    const int wid = tid >> 5, lane = tid & 31;
    const int grp = lane >> 2, qd = lane & 3;
    const int wm = (wid >> 2) * 64;     // 0 / 64
    const int wn = (wid & 3) * 32;      // 0..96
    const int bx = blockIdx.x;
    const int m0 = blockIdx.y * G_BM;

    const bool isQ = (bx < 16);
    int h = 0, which = 0, cnt = Mrows;
    const float* Wbase;
    if (isQ) {
        Wbase = g_wr + (size_t)(bx * G_BN) * Kdim;
    } else {
        const int t = bx - 16;
        h = t >> 1; which = t & 1;
        cnt = g_cnt[h];
        if (m0 >= cnt) return;
        Wbase = g_wr + (size_t)((which ? 2 * Cdim : Cdim) + h * HD) * Kdim;
    }

    // hoist per-thread A row pointers (gathered for KV path)
    const int lr = tid >> 3;            // 0..31
    const int lc = (tid & 7) << 2;      // 0,4,...,28
    const float* arow[4];
    #pragma unroll
    for (int i = 0; i < 4; i++) {
        int r = m0 + lr + i * 32;
        int tok;
        if (isQ) tok = r;
        else { if (r >= cnt) r = cnt - 1; tok = g_list[h * Mrows + r]; }
        arow[i] = g_xr + (size_t)tok * Kdim;
    }

    float acc[4][4][4];
    #pragma unroll
    for (int mt = 0; mt < 4; mt++)
        #pragma unroll
        for (int nt = 0; nt < 4; nt++)
            #pragma unroll
            for (int r = 0; r < 4; r++) acc[mt][nt][r] = 0.f;

    // prologue: issue stages 0,1
    #pragma unroll
    for (int s = 0; s < 2; s++) {
        unsigned* As = gsm + s * G_STSZ;
        unsigned* Bs = As + G_ASZ;
        const int kt = s * G_BK;
        #pragma unroll
        for (int i = 0; i < 4; i++) {
            int r = lr + i * 32;
            cp16(As + r * 36 + lc, arow[i] + kt + lc);
            cp16(Bs + r * 36 + lc, Wbase + (size_t)r * Kdim + kt + lc);
        }
        CP_COMMIT();
    }

    const int NIT = Kdim / G_BK;        // 64
    for (int it = 0; it < NIT; it++) {
        cp_wait<1>();
        __syncthreads();
        if (it + 2 < NIT) {
            int s = (it + 2) % G_STG;
            unsigned* As = gsm + s * G_STSZ;
            unsigned* Bs = As + G_ASZ;
            const int kt = (it + 2) * G_BK;
            #pragma unroll
            for (int i = 0; i < 4; i++) {
                int r = lr + i * 32;
                cp16(As + r * 36 + lc, arow[i] + kt + lc);
                cp16(Bs + r * 36 + lc, Wbase + (size_t)r * Kdim + kt + lc);
            }
        }
        CP_COMMIT();

        const unsigned* As = gsm + (it % G_STG) * G_STSZ;
        const unsigned* Bs = As + G_ASZ;
        #pragma unroll
        for (int ks = 0; ks < G_BK; ks += 8) {
            unsigned a[4][4], b[4][2];
            #pragma unroll
            for (int mt = 0; mt < 4; mt++) {
                int rb = wm + mt * 16;
                a[mt][0] = As[(rb + grp) * 36 + ks + qd];
                a[mt][1] = As[(rb + grp + 8) * 36 + ks + qd];
                a[mt][2] = As[(rb + grp) * 36 + ks + qd + 4];
                a[mt][3] = As[(rb + grp + 8) * 36 + ks + qd + 4];
            }
            #pragma unroll
            for (int nt = 0; nt < 4; nt++) {
                int nb = wn + nt * 8;
                b[nt][0] = Bs[(nb + grp) * 36 + ks + qd];
                b[nt][1] = Bs[(nb + grp) * 36 + ks + qd + 4];
            }
            #pragma unroll
            for (int mt = 0; mt < 4; mt++)
                #pragma unroll
                for (int nt = 0; nt < 4; nt++)
                    mma_tf32(acc[mt][nt], a[mt], b[nt]);
        }
    }

    // epilogue
    if (isQ) {
        #pragma unroll
        for (int mt = 0; mt < 4; mt++) {
            int r0 = m0 + wm + mt * 16 + grp;
            #pragma unroll
            for (int nt = 0; nt < 4; nt++) {
                int cc = bx * G_BN + wn + nt * 8 + 2 * qd;
                *(float2*)(g_q + (size_t)r0 * Cdim + cc) =
                    make_float2(rndtf(acc[mt][nt][0]), rndtf(acc[mt][nt][1]));
                *(float2*)(g_q + (size_t)(r0 + 8) * Cdim + cc) =
                    make_float2(rndtf(acc[mt][nt][2]), rndtf(acc[mt][nt][3]));
            }
        }
    } else {
        float* dst = which ? g_vsh : g_ksh;
        #pragma unroll
        for (int mt = 0; mt < 4; mt++) {
            #pragma unroll
            for (int half = 0; half < 2; half++) {
                int gr = m0 + wm + mt * 16 + grp + half * 8;
                if (gr < cnt) {
                    int tok = g_list[h * Mrows + gr];
                    float scale = which ? g_top1[tok] : 1.f;
                    #pragma unroll
                    for (int nt = 0; nt < 4; nt++) {
                        int cc = wn + nt * 8 + 2 * qd;
                        float v0 = acc[mt][nt][half * 2 + 0];
                        float v1 = acc[mt][nt][half * 2 + 1];
                        if (which) { v0 *= scale; v1 *= scale; }
                        *(float2*)(dst + (size_t)tok * HD + cc) =
                            make_float2(rndtf(v0), rndtf(v1));
                    }
                }
            }
        }
    }
}

// ============================================================================
// Kernel 4: causal flash attention, tf32 mma.sync, cp.async double-buffered K/V,
// Q fragments hoisted to registers (Q smem region reused for P).
// ============================================================================
#define BQ   128
#define BKV  64
#define QST  132
#define KST  132
#define VST  136
#define PST  68
#define A_QWORDS (BQ * QST)
#define A_KSTG   (BKV * KST)
#define A_VSTG   (BKV * VST)
#define A_SMEM_WORDS (A_QWORDS + 2 * A_KSTG + 2 * A_VSTG)
#define A_SMEM_BYTES (A_SMEM_WORDS * 4)

__global__ __launch_bounds__(256, 1) void attn_kernel(float* __restrict__ out) {
    extern __shared__ unsigned sm[];
    unsigned* Qs = sm;
    unsigned* Ks = sm + A_QWORDS;
    unsigned* Vs = Ks + 2 * A_KSTG;

    const int qt = gridDim.x - 1 - blockIdx.x;
    const int bh = blockIdx.y;
    const int b = bh >> 4, h = bh & 15;
    const int qbase = qt * BQ;
    const int tid = threadIdx.x, wid = tid >> 5, lane = tid & 31;
    const int grp = lane >> 2, qd = lane & 3;

    const float* qg = g_q + (size_t)(b * Tdim + qbase) * Cdim + h * HD;
    const float* kg = g_ksh + (size_t)b * Tdim * HD;
    const float* vg = g_vsh + (size_t)b * Tdim * HD;

    const int cr = tid >> 5;
    const int ccol = (tid & 31) << 2;

    #pragma unroll
    for (int i = 0; i < 16; i++) {
        int r = cr + i * 8;
        cp16(Qs + r * QST + ccol, qg + (size_t)r * Cdim + ccol);
    }
    #pragma unroll
    for (int i = 0; i < 8; i++) {
        int r = cr + i * 8;
        cp16(Ks + r * KST + ccol, kg + (size_t)r * HD + ccol);
        cp16(Vs + r * VST + ccol, vg + (size_t)r * HD + ccol);
    }
    CP_COMMIT();
    cp_wait<0>();
    __syncthreads();

    unsigned qf[16][4];
    {
        const unsigned* qb = Qs + (wid * 16) * QST;
        #pragma unroll
        for (int kk = 0; kk < 16; kk++) {
            qf[kk][0] = qb[grp * QST + kk * 8 + qd];
            qf[kk][1] = qb[(grp + 8) * QST + kk * 8 + qd];
            qf[kk][2] = qb[grp * QST + kk * 8 + qd + 4];
            qf[kk][3] = qb[(grp + 8) * QST + kk * 8 + qd + 4];
        }
    }
    __syncthreads();

    float o[16][4];
    #pragma unroll
    for (int n = 0; n < 16; n++)
        #pragma unroll
        for (int r = 0; r < 4; r++) o[n][r] = 0.f;
    float mi0 = -1e30f, mi1 = -1e30f, li0 = 0.f, li1 = 0.f;

    const int qrow_last = qbase + wid * 16 + 15;
    const int ntiles = (qbase + BQ) / BKV;
    const float sc = 0.08838834764831845f;
    unsigned* pw = Qs + wid * 16 * PST;

    for (int t = 0; t < ntiles; t++) {
        const int kstart = t * BKV;
        cp_wait<0>();
        __syncthreads();
        if (t + 1 < ntiles) {
            const int st = (t + 1) & 1;
            const int ks2 = (t + 1) * BKV;
            unsigned* kd = Ks + st * A_KSTG;
            unsigned* vd = Vs + st * A_VSTG;
            #pragma unroll
            for (int i = 0; i < 8; i++) {
                int r = cr + i * 8;
                cp16(kd + r * KST + ccol, kg + (size_t)(ks2 + r) * HD + ccol);
                cp16(vd + r * VST + ccol, vg + (size_t)(ks2 + r) * HD + ccol);
            }
        }
        CP_COMMIT();

        if (kstart <= qrow_last) {
            const unsigned* Kc = Ks + (t & 1) * A_KSTG;
            const unsigned* Vc = Vs + (t & 1) * A_VSTG;

            float s[8][4];
            #pragma unroll
            for (int n = 0; n < 8; n++)
                #pragma unroll
                for (int r = 0; r < 4; r++) s[n][r] = 0.f;

            #pragma unroll
            for (int kk = 0; kk < 16; kk++) {
                #pragma unroll
                for (int nt = 0; nt < 8; nt++) {
                    unsigned bb[2];
                    bb[0] = Kc[(nt * 8 + grp) * KST + kk * 8 + qd];
                    bb[1] = Kc[(nt * 8 + grp) * KST + kk * 8 + qd + 4];
                    mma_tf32(s[nt], qf[kk], bb);
                }
            }

            const int row0 = qbase + wid * 16 + grp;
            const int row1 = row0 + 8;
            #pragma unroll
            for (int nt = 0; nt < 8; nt++) {
                int cbase = kstart + nt * 8 + 2 * qd;
                s[nt][0] = (cbase     <= row0) ? s[nt][0] * sc : -1e30f;
                s[nt][1] = (cbase + 1 <= row0) ? s[nt][1] * sc : -1e30f;
                s[nt][2] = (cbase     <= row1) ? s[nt][2] * sc : -1e30f;
                s[nt][3] = (cbase + 1 <= row1) ? s[nt][3] * sc : -1e30f;
            }

            float rm0 = -1e30f, rm1 = -1e30f;
            #pragma unroll
            for (int nt = 0; nt < 8; nt++) {
                rm0 = fmaxf(rm0, fmaxf(s[nt][0], s[nt][1]));
                rm1 = fmaxf(rm1, fmaxf(s[nt][2], s[nt][3]));
            }
            #pragma unroll
            for (int off = 1; off < 4; off <<= 1) {
                rm0 = fmaxf(rm0, __shfl_xor_sync(0xffffffffu, rm0, off));
                rm1 = fmaxf(rm1, __shfl_xor_sync(0xffffffffu, rm1, off));
            }
            const float mn0 = fmaxf(mi0, rm0), mn1 = fmaxf(mi1, rm1);
            const float f0 = __expf(mi0 - mn0), f1 = __expf(mi1 - mn1);
            mi0 = mn0; mi1 = mn1;

            float ls0 = 0.f, ls1 = 0.f;
            #pragma unroll
            for (int nt = 0; nt < 8; nt++) {
                float p0 = __expf(s[nt][0] - mn0), p1 = __expf(s[nt][1] - mn0);
                float p2 = __expf(s[nt][2] - mn1), p3 = __expf(s[nt][3] - mn1);
                ls0 += p0 + p1; ls1 += p2 + p3;
                int c = nt * 8 + 2 * qd;
                pw[grp * PST + c]           = f2tf(p0);
                pw[grp * PST + c + 1]       = f2tf(p1);
                pw[(grp + 8) * PST + c]     = f2tf(p2);
                pw[(grp + 8) * PST + c + 1] = f2tf(p3);
            }
            #pragma unroll
            for (int off = 1; off < 4; off <<= 1) {
                ls0 += __shfl_xor_sync(0xffffffffu, ls0, off);
                ls1 += __shfl_xor_sync(0xffffffffu, ls1, off);
            }
            li0 = li0 * f0 + ls0;
            li1 = li1 * f1 + ls1;
            #pragma unroll
            for (int nt = 0; nt < 16; nt++) {
                o[nt][0] *= f0; o[nt][1] *= f0;
                o[nt][2] *= f1; o[nt][3] *= f1;
            }
            __syncwarp();

            #pragma unroll
            for (int kk = 0; kk < 8; kk++) {
                unsigned a[4];
                a[0] = pw[grp * PST + kk * 8 + qd];
                a[1] = pw[(grp + 8) * PST + kk * 8 + qd];
                a[2] = pw[grp * PST + kk * 8 + qd + 4];
                a[3] = pw[(grp + 8) * PST + kk * 8 + qd + 4];
                #pragma unroll
                for (int nt = 0; nt < 16; nt++) {
                    unsigned bb[2];
                    bb[0] = Vc[(kk * 8 + qd) * VST + nt * 8 + grp];
                    bb[1] = Vc[(kk * 8 + qd + 4) * VST + nt * 8 + grp];
                    mma_tf32(o[nt], a, bb);
                }
            }
        }
    }

    const float inv0 = 1.f / li0, inv1 = 1.f / li1;
    const size_t r0 = (size_t)(b * Tdim + qbase + wid * 16 + grp) * Cdim;
    const size_t r1 = r0 + (size_t)8 * Cdim;
    #pragma unroll
    for (int nt = 0; nt < 16; nt++) {
        int c = h * HD + nt * 8 + 2 * qd;
        *(float2*)(out + r0 + c) = make_float2(o[nt][0] * inv0, o[nt][1] * inv0);
        *(float2*)(out + r1 + c) = make_float2(o[nt][2] * inv1, o[nt][3] * inv1);
    }
}

// ============================================================================
// host launcher
// ============================================================================
extern "C" void kernel_launch(void* const* d_in, const int* in_sizes, int n_in,
                              void* d_out, int out_size) {
    const float* x    = (const float*)d_in[0];
    const float* Wg   = (const float*)d_in[1];
    const float* Wqkv = (const float*)d_in[2];
    float* out = (float*)d_out;

    static int attr_set = 0;
    if (!attr_set) {
        cudaFuncSetAttribute(fused_gemm, cudaFuncAttributeMaxDynamicSharedMemorySize, G_SMEM_BYTES);
        cudaFuncSetAttribute(attn_kernel, cudaFuncAttributeMaxDynamicSharedMemorySize, A_SMEM_BYTES);
        attr_set = 1;
    }

    // pre-round x and W_qkv to tf32
    {
        float* xr; cudaGetSymbolAddress((void**)&xr, g_xr);
        float* wr; cudaGetSymbolAddress((void**)&wr, g_wr);
        int nx4 = Mrows * Kdim / 4;
        int nw4 = Ncols * Kdim / 4;
        round_kernel<<<(nx4 + 255) / 256, 256>>>(x, xr, nx4);
        round_kernel<<<(nw4 + 255) / 256, 256>>>(Wqkv, wr, nw4);
    }

    gate_kernel<<<Mrows / GATE_TOKS, 512>>>(x, Wg);
    zero_cnt_kernel<<<1, 32>>>();
    build_groups_kernel<<<Mrows / 256, 256>>>();

    dim3 gg(48, 32);                          // x: 16 Q-ntiles + 32 KV slots
    fused_gemm<<<gg, 256, G_SMEM_BYTES>>>();

    dim3 ga(Tdim / BQ, Bdim * Hn);            // 16 x 32
    attn_kernel<<<ga, 256, A_SMEM_BYTES>>>(out);
}

// round 11
// speedup vs baseline: 3.2309x; 1.0215x over previous
#include <cuda_runtime.h>
#include <cuda_bf16.h>
#include <cstdint>

// ---------------- problem constants ----------------
#define Bdim 2
#define Tdim 2048
#define Cdim 2048
#define Hn   16
#define HD   128
#define Mrows (Bdim * Tdim)   // 4096
#define Ncols (3 * Cdim)      // 6144
#define Kdim  Cdim            // 2048

// ---------------- device scratch (no runtime alloc allowed) ----------------
__device__ float g_xr [(size_t)Mrows * Kdim];    // tf32-rounded x
__device__ float g_wr [(size_t)Ncols * Kdim];    // tf32-rounded W_qkv
__device__ float g_q  [(size_t)Mrows * Cdim];    // Q only (tf32-rounded)
__device__ int   g_idx [Mrows];
__device__ float g_top1[Mrows];
__device__ int   g_cnt [Hn];
__device__ int   g_list[Hn * Mrows];
__device__ float g_ksh [Mrows * HD];             // K, head-dim pair-interleaved
__device__ float g_vshT[(size_t)HD * Mrows];     // V^T, token pair-interleaved

// ---------------- helpers ----------------
__device__ __forceinline__ unsigned f2tf(float x) {
    unsigned r;
    asm("cvt.rna.tf32.f32 %0, %1;" : "=r"(r) : "f"(x));
    return r;
}
__device__ __forceinline__ float rndtf(float x) { return __uint_as_float(f2tf(x)); }

__device__ __forceinline__ void mma_tf32(float* c, const unsigned* a, const unsigned* b) {
    asm volatile(
        "mma.sync.aligned.m16n8k8.row.col.f32.tf32.tf32.f32 "
        "{%0,%1,%2,%3}, {%4,%5,%6,%7}, {%8,%9}, {%0,%1,%2,%3};"
        : "+f"(c[0]), "+f"(c[1]), "+f"(c[2]), "+f"(c[3])
        : "r"(a[0]), "r"(a[1]), "r"(a[2]), "r"(a[3]), "r"(b[0]), "r"(b[1]));
}

__device__ __forceinline__ void cp16(unsigned* smem_dst, const float* gmem_src) {
    unsigned s = (unsigned)__cvta_generic_to_shared(smem_dst);
    asm volatile("cp.async.cg.shared.global [%0], [%1], 16;\n" :: "r"(s), "l"(gmem_src));
}
#define CP_COMMIT() asm volatile("cp.async.commit_group;\n" ::)
template <int N> __device__ __forceinline__ void cp_wait() {
    asm volatile("cp.async.wait_group %0;\n" :: "n"(N));
}
// pair-interleave perm within 8-blocks: logical j -> physical (j&3)*2 + (j>>2)
__device__ __forceinline__ int pperm(int j) { return ((j & 3) << 1) | (j >> 2); }

// ============================================================================
// Kernel 0: pre-round an fp32 array to tf32 (rna)
// ============================================================================
__global__ __launch_bounds__(256) void round_kernel(const float* __restrict__ src,
                                                    float* __restrict__ dst, int n4) {
    int i = blockIdx.x * 256 + threadIdx.x;
    if (i < n4) {
        float4 v = ((const float4*)src)[i];
        v.x = rndtf(v.x); v.y = rndtf(v.y); v.z = rndtf(v.z); v.w = rndtf(v.w);
        ((float4*)dst)[i] = v;
    }
}

// ============================================================================
// Kernel 1: gating logits (fp32 exact) -> argmax + top-1 softmax value
// ============================================================================
#define GATE_TOKS 8
__global__ __launch_bounds__(512) void gate_kernel(const float* __restrict__ x,
                                                   const float* __restrict__ Wg) {
    const int wid = threadIdx.x >> 5, lane = threadIdx.x & 31;
    __shared__ float sl[Hn];
    const float* wr = Wg + (size_t)wid * Cdim;
    const int m0 = blockIdx.x * GATE_TOKS;
    for (int tm = 0; tm < GATE_TOKS; tm++) {
        const int m = m0 + tm;
        const float* xr = x + (size_t)m * Cdim;
        float s = 0.f;
        #pragma unroll 8
        for (int k = lane; k < Cdim; k += 32) s += xr[k] * wr[k];
        #pragma unroll
        for (int o = 16; o; o >>= 1) s += __shfl_xor_sync(0xffffffffu, s, o);
        if (lane == 0) sl[wid] = s;
        __syncthreads();
        if (threadIdx.x == 0) {
            float mx = sl[0]; int bi = 0;
            #pragma unroll
            for (int h = 1; h < Hn; h++) { if (sl[h] > mx) { mx = sl[h]; bi = h; } }
            float den = 0.f;
            #pragma unroll
            for (int h = 0; h < Hn; h++) den += __expf(sl[h] - mx);
            g_idx[m]  = bi;
            g_top1[m] = 1.f / den;
        }
        __syncthreads();
    }
}

// ============================================================================
// Kernel 1b: group tokens by selected head
// ============================================================================
__global__ void zero_cnt_kernel() {
    if (threadIdx.x < Hn) g_cnt[threadIdx.x] = 0;
}
__global__ __launch_bounds__(256) void build_groups_kernel() {
    int m = blockIdx.x * 256 + threadIdx.x;
    int h = g_idx[m];
    int pos = atomicAdd(&g_cnt[h], 1);
    g_list[h * Mrows + pos] = m;
}

// ============================================================================
// Kernel 2: fused GEMM (tf32 mma.sync, cp.async 3-stage, 2 CTAs/SM)
//   blockIdx.x in [0,16):  Q tiles   -> g_q
//   blockIdx.x in [16,48): KV tiles  -> g_ksh (d pair-interleaved) /
//                                       g_vshT (transposed, token-interleaved)
// ============================================================================
#define G_BM 128
#define G_BN 128
#define G_BK 32
#define G_STG 3
#define G_ASZ (G_BM * 36)
#define G_STSZ (2 * G_ASZ)
#define G_SMEM_BYTES (G_STG * G_STSZ * 4)

__global__ __launch_bounds__(256, 2) void fused_gemm() {
    extern __shared__ unsigned gsm[];
    const int tid = threadIdx.x;
    const int wid = tid >> 5, lane = tid & 31;
    const int grp = lane >> 2, qd = lane & 3;
    const int wm = (wid >> 2) * 64;
    const int wn = (wid & 3) * 32;
    const int bx = blockIdx.x;
    const int m0 = blockIdx.y * G_BM;

    const bool isQ = (bx < 16);
    int h = 0, which = 0, cnt = Mrows;
    const float* Wbase;
    if (isQ) {
        Wbase = g_wr + (size_t)(bx * G_BN) * Kdim;
    } else {
        const int t = bx - 16;
        h = t >> 1; which = t & 1;
        cnt = g_cnt[h];
        if (m0 >= cnt) return;
        Wbase = g_wr + (size_t)((which ? 2 * Cdim : Cdim) + h * HD) * Kdim;
    }

    const int lr = tid >> 3;
    const int lc = (tid & 7) << 2;
    const float* arow[4];
    #pragma unroll
    for (int i = 0; i < 4; i++) {
        int r = m0 + lr + i * 32;
        int tok;
        if (isQ) tok = r;
        else { if (r >= cnt) r = cnt - 1; tok = g_list[h * Mrows + r]; }
        arow[i] = g_xr + (size_t)tok * Kdim;
    }

    float acc[4][4][4];
    #pragma unroll
    for (int mt = 0; mt < 4; mt++)
        #pragma unroll
        for (int nt = 0; nt < 4; nt++)
            #pragma unroll
            for (int r = 0; r < 4; r++) acc[mt][nt][r] = 0.f;

    #pragma unroll
    for (int s = 0; s < 2; s++) {
        unsigned* As = gsm + s * G_STSZ;
        unsigned* Bs = As + G_ASZ;
        const int kt = s * G_BK;
        #pragma unroll
        for (int i = 0; i < 4; i++) {
            int r = lr + i * 32;
            cp16(As + r * 36 + lc, arow[i] + kt + lc);
            cp16(Bs + r * 36 + lc, Wbase + (size_t)r * Kdim + kt + lc);
        }
        CP_COMMIT();
    }

    const int NIT = Kdim / G_BK;
    for (int it = 0; it < NIT; it++) {
        cp_wait<1>();
        __syncthreads();
        if (it + 2 < NIT) {
            int s = (it + 2) % G_STG;
            unsigned* As = gsm + s * G_STSZ;
            unsigned* Bs = As + G_ASZ;
            const int kt = (it + 2) * G_BK;
            #pragma unroll
            for (int i = 0; i < 4; i++) {
                int r = lr + i * 32;
                cp16(As + r * 36 + lc, arow[i] + kt + lc);
                cp16(Bs + r * 36 + lc, Wbase + (size_t)r * Kdim + kt + lc);
            }
        }
        CP_COMMIT();

        const unsigned* As = gsm + (it % G_STG) * G_STSZ;
        const unsigned* Bs = As + G_ASZ;
        #pragma unroll
        for (int ks = 0; ks < G_BK; ks += 8) {
            unsigned a[4][4], b[4][2];
            #pragma unroll
            for (int mt = 0; mt < 4; mt++) {
                int rb = wm + mt * 16;
                a[mt][0] = As[(rb + grp) * 36 + ks + qd];
                a[mt][1] = As[(rb + grp + 8) * 36 + ks + qd];
                a[mt][2] = As[(rb + grp) * 36 + ks + qd + 4];
                a[mt][3] = As[(rb + grp + 8) * 36 + ks + qd + 4];
            }
            #pragma unroll
            for (int nt = 0; nt < 4; nt++) {
                int nb = wn + nt * 8;
                b[nt][0] = Bs[(nb + grp) * 36 + ks + qd];
                b[nt][1] = Bs[(nb + grp) * 36 + ks + qd + 4];
            }
            #pragma unroll
            for (int mt = 0; mt < 4; mt++)
                #pragma unroll
                for (int nt = 0; nt < 4; nt++)
                    mma_tf32(acc[mt][nt], a[mt], b[nt]);
        }
    }

    // epilogue
    if (isQ) {
        #pragma unroll
        for (int mt = 0; mt < 4; mt++) {
            int r0 = m0 + wm + mt * 16 + grp;
            #pragma unroll
            for (int nt = 0; nt < 4; nt++) {
                int cc = bx * G_BN + wn + nt * 8 + 2 * qd;
                *(float2*)(g_q + (size_t)r0 * Cdim + cc) =
                    make_float2(rndtf(acc[mt][nt][0]), rndtf(acc[mt][nt][1]));
                *(float2*)(g_q + (size_t)(r0 + 8) * Cdim + cc) =
                    make_float2(rndtf(acc[mt][nt][2]), rndtf(acc[mt][nt][3]));
            }
        }
    } else {
        // physical positions of logical j0=2qd, j1=2qd+1 within the 8-block
        const int pp0 = (qd < 2) ? 4 * qd : 4 * qd - 7;
        const int pp1 = (qd < 2) ? 4 * qd + 2 : 4 * qd - 5;
        #pragma unroll
        for (int mt = 0; mt < 4; mt++) {
            #pragma unroll
            for (int half = 0; half < 2; half++) {
                int gr = m0 + wm + mt * 16 + grp + half * 8;
                if (gr < cnt) {
                    int tok = g_list[h * Mrows + gr];
                    if (which == 0) {
                        // K: pair-interleave the head dim
                        float* dst = g_ksh + (size_t)tok * HD;
                        #pragma unroll
                        for (int nt = 0; nt < 4; nt++) {
                            int base = wn + nt * 8;
                            dst[base + pp0] = rndtf(acc[mt][nt][half * 2 + 0]);
                            dst[base + pp1] = rndtf(acc[mt][nt][half * 2 + 1]);
                        }
                    } else {
                        // V: transpose to [d][token'], token pair-interleaved
                        float scale = g_top1[tok];
                        int mp = (tok & ~7) | pperm(tok & 7);
                        #pragma unroll
                        for (int nt = 0; nt < 4; nt++) {
                            int d = wn + nt * 8 + 2 * qd;
                            g_vshT[(size_t)d * Mrows + mp] =
                                rndtf(acc[mt][nt][half * 2 + 0] * scale);
                            g_vshT[(size_t)(d + 1) * Mrows + mp] =
                                rndtf(acc[mt][nt][half * 2 + 1] * scale);
                        }
                    }
                }
            }
        }
    }
}

// ============================================================================
// Kernel 4: causal flash attention, paired-fragment LDS.64 layouts.
// BQ=64 (4 warps x 16 rows), BKV=32, 2 CTAs/SM.
// smem: K 2x32x136 | V^T 2x128x40 | P 4x16x40 = 21504 words (86 KB).
// ============================================================================
#define BQ   64
#define BKV  32
#define KSTw 136
#define VSTw 40
#define PSTw 40
#define A_KSTG (BKV * KSTw)                 // 4352
#define A_VSTG (HD * VSTw)                  // 5120
#define A_POFF (2 * A_KSTG + 2 * A_VSTG)    // 18944
#define A_WORDS (A_POFF + 4 * 16 * PSTw)    // 21504
#define A_SMEM_BYTES (A_WORDS * 4)

__global__ __launch_bounds__(128, 2) void attn_kernel(float* __restrict__ out) {
    extern __shared__ unsigned sm[];
    unsigned* Ks = sm;
    unsigned* Vs = sm + 2 * A_KSTG;
    unsigned* Ps = sm + A_POFF;

    const int qt = gridDim.x - 1 - blockIdx.x;   // heavy tiles first
    const int bh = blockIdx.y;
    const int b = bh >> 4, h = bh & 15;
    const int qbase = qt * BQ;
    const int tid = threadIdx.x, wid = tid >> 5, lane = tid & 31;
    const int grp = lane >> 2, qd = lane & 3;

    const float* kg = g_ksh + (size_t)b * Tdim * HD;
    const float* vgT = g_vshT + (size_t)b * Tdim;   // + d*Mrows + t

    // Q fragments straight from gmem (already tf32-rounded bits)
    const float* q0 = g_q + (size_t)(b * Tdim + qbase + wid * 16 + grp) * Cdim + h * HD;
    const float* q1 = q0 + (size_t)8 * Cdim;
    unsigned qf[16][4];
    #pragma unroll
    for (int kk = 0; kk < 16; kk++) {
        qf[kk][0] = __float_as_uint(q0[kk * 8 + qd]);
        qf[kk][1] = __float_as_uint(q1[kk * 8 + qd]);
        qf[kk][2] = __float_as_uint(q0[kk * 8 + qd + 4]);
        qf[kk][3] = __float_as_uint(q1[kk * 8 + qd + 4]);
    }

    // prefetch tile 0 (K: 1024 chunks, V: 1024 chunks; 128 threads)
    #pragma unroll
    for (int i = 0; i < 8; i++) {
        int c = tid + i * 128;
        int kr = c >> 5, kc = (c & 31) << 2;        // K: 32 rows x 32 chunks
        cp16(Ks + kr * KSTw + kc, kg + (size_t)kr * HD + kc);
        int vr = c >> 3, vc = (c & 7) << 2;         // V^T: 128 rows x 8 chunks
        cp16(Vs + vr * VSTw + vc, vgT + (size_t)vr * Mrows + vc);
    }
    CP_COMMIT();

    float o[16][4];
    #pragma unroll
    for (int n = 0; n < 16; n++)
        #pragma unroll
        for (int r = 0; r < 4; r++) o[n][r] = 0.f;
    float mi0 = -1e30f, mi1 = -1e30f, li0 = 0.f, li1 = 0.f;

    const int qrow_last = qbase + wid * 16 + 15;
    const int ntiles = (qbase + BQ) / BKV;
    const float sc = 0.08838834764831845f;      // 1/sqrt(128)
    unsigned* pw = Ps + (wid * 16) * PSTw;
    const int pp0 = (qd < 2) ? 4 * qd : 4 * qd - 7;
    const int pp1 = (qd < 2) ? 4 * qd + 2 : 4 * qd - 5;

    for (int t = 0; t < ntiles; t++) {
        const int kstart = t * BKV;
        cp_wait<0>();
        __syncthreads();
        if (t + 1 < ntiles) {
            const int st = (t + 1) & 1;
            const int ks2 = (t + 1) * BKV;
            unsigned* kd = Ks + st * A_KSTG;
            unsigned* vd = Vs + st * A_VSTG;
            #pragma unroll
            for (int i = 0; i < 8; i++) {
                int c = tid + i * 128;
                int kr = c >> 5, kc = (c & 31) << 2;
                cp16(kd + kr * KSTw + kc, kg + (size_t)(ks2 + kr) * HD + kc);
                int vr = c >> 3, vc = (c & 7) << 2;
                cp16(vd + vr * VSTw + vc, vgT + (size_t)vr * Mrows + ks2 + vc);
            }
        }
        CP_COMMIT();

        if (kstart <= qrow_last) {
            const unsigned* Kc = Ks + (t & 1) * A_KSTG;
            const unsigned* Vc = Vs + (t & 1) * A_VSTG;

            float s[4][4];
            #pragma unroll
            for (int n = 0; n < 4; n++)
                #pragma unroll
                for (int r = 0; r < 4; r++) s[n][r] = 0.f;

            // S = Q @ K^T  (paired LDS.64 B-fragments)
            #pragma unroll
            for (int kk = 0; kk < 16; kk++) {
                #pragma unroll
                for (int nt = 0; nt < 4; nt++) {
                    uint2 bb = *(const uint2*)(Kc + (nt * 8 + grp) * KSTw + kk * 8 + 2 * qd);
                    mma_tf32(s[nt], qf[kk], (const unsigned*)&bb);
                }
            }

            // scale + causal mask
            const int row0 = qbase + wid * 16 + grp;
            const int row1 = row0 + 8;
            #pragma unroll
            for (int nt = 0; nt < 4; nt++) {
                int cbase = kstart + nt * 8 + 2 * qd;
                s[nt][0] = (cbase     <= row0) ? s[nt][0] * sc : -1e30f;
                s[nt][1] = (cbase + 1 <= row0) ? s[nt][1] * sc : -1e30f;
                s[nt][2] = (cbase     <= row1) ? s[nt][2] * sc : -1e30f;
                s[nt][3] = (cbase + 1 <= row1) ? s[nt][3] * sc : -1e30f;
            }

            // online softmax
            float rm0 = -1e30f, rm1 = -1e30f;
            #pragma unroll
            for (int nt = 0; nt < 4; nt++) {
                rm0 = fmaxf(rm0, fmaxf(s[nt][0], s[nt][1]));
                rm1 = fmaxf(rm1, fmaxf(s[nt][2], s[nt][3]));
            }
            #pragma unroll
            for (int off = 1; off < 4; off <<= 1) {
                rm0 = fmaxf(rm0, __shfl_xor_sync(0xffffffffu, rm0, off));
                rm1 = fmaxf(rm1, __shfl_xor_sync(0xffffffffu, rm1, off));
            }
            const float mn0 = fmaxf(mi0, rm0), mn1 = fmaxf(mi1, rm1);
            const float f0 = __expf(mi0 - mn0), f1 = __expf(mi1 - mn1);
            mi0 = mn0; mi1 = mn1;

            float ls0 = 0.f, ls1 = 0.f;
            #pragma unroll
            for (int nt = 0; nt < 4; nt++) {
                float p0 = __expf(s[nt][0] - mn0), p1 = __expf(s[nt][1] - mn0);
                float p2 = __expf(s[nt][2] - mn1), p3 = __expf(s[nt][3] - mn1);
                ls0 += p0 + p1; ls1 += p2 + p3;
                int cb = nt * 8;
                pw[grp * PSTw + cb + pp0]       = f2tf(p0);
                pw[grp * PSTw + cb + pp1]       = f2tf(p1);
                pw[(grp + 8) * PSTw + cb + pp0] = f2tf(p2);
                pw[(grp + 8) * PSTw + cb + pp1] = f2tf(p3);
            }
            #pragma unroll
            for (int off = 1; off < 4; off <<= 1) {
                ls0 += __shfl_xor_sync(0xffffffffu, ls0, off);
                ls1 += __shfl_xor_sync(0xffffffffu, ls1, off);
            }
            li0 = li0 * f0 + ls0;
            li1 = li1 * f1 + ls1;
            #pragma unroll
            for (int nt = 0; nt < 16; nt++) {
                o[nt][0] *= f0; o[nt][1] *= f0;
                o[nt][2] *= f1; o[nt][3] *= f1;
            }
            __syncwarp();

            // O += P @ V  (paired LDS.64 A- and B-fragments)
            #pragma unroll
            for (int kk = 0; kk < 4; kk++) {
                uint2 aa0 = *(const uint2*)(pw + grp * PSTw + kk * 8 + 2 * qd);
                uint2 aa1 = *(const uint2*)(pw + (grp + 8) * PSTw + kk * 8 + 2 * qd);
                unsigned a[4] = {aa0.x, aa1.x, aa0.y, aa1.y};
                #pragma unroll
                for (int nt = 0; nt < 16; nt++) {
                    uint2 bb = *(const uint2*)(Vc + (nt * 8 + grp) * VSTw + kk * 8 + 2 * qd);
                    mma_tf32(o[nt], a, (const unsigned*)&bb);
                }
            }
        }
    }

    // normalize + write: out[b, t, h*HD + d]
    const float inv0 = 1.f / li0, inv1 = 1.f / li1;
    const size_t r0 = (size_t)(b * Tdim + qbase + wid * 16 + grp) * Cdim;
    const size_t r1 = r0 + (size_t)8 * Cdim;
    #pragma unroll
    for (int nt = 0; nt < 16; nt++) {
        int c = h * HD + nt * 8 + 2 * qd;
        *(float2*)(out + r0 + c) = make_float2(o[nt][0] * inv0, o[nt][1] * inv0);
        *(float2*)(out + r1 + c) = make_float2(o[nt][2] * inv1, o[nt][3] * inv1);
    }
}

// ============================================================================
// host launcher
// ============================================================================
extern "C" void kernel_launch(void* const* d_in, const int* in_sizes, int n_in,
                              void* d_out, int out_size) {
    const float* x    = (const float*)d_in[0];
    const float* Wg   = (const float*)d_in[1];
    const float* Wqkv = (const float*)d_in[2];
    float* out = (float*)d_out;

    static int attr_set = 0;
    if (!attr_set) {
        cudaFuncSetAttribute(fused_gemm, cudaFuncAttributeMaxDynamicSharedMemorySize, G_SMEM_BYTES);
        cudaFuncSetAttribute(attn_kernel, cudaFuncAttributeMaxDynamicSharedMemorySize, A_SMEM_BYTES);
        attr_set = 1;
    }

    // pre-round x and W_qkv to tf32
    {
        float* xr; cudaGetSymbolAddress((void**)&xr, g_xr);
        float* wr; cudaGetSymbolAddress((void**)&wr, g_wr);
        int nx4 = Mrows * Kdim / 4;
        int nw4 = Ncols * Kdim / 4;
        round_kernel<<<(nx4 + 255) / 256, 256>>>(x, xr, nx4);
        round_kernel<<<(nw4 + 255) / 256, 256>>>(Wqkv, wr, nw4);
    }

    gate_kernel<<<Mrows / GATE_TOKS, 512>>>(x, Wg);
    zero_cnt_kernel<<<1, 32>>>();
    build_groups_kernel<<<Mrows / 256, 256>>>();

    dim3 gg(48, 32);                          // 16 Q-ntiles + 32 KV slots
    fused_gemm<<<gg, 256, G_SMEM_BYTES>>>();

    dim3 ga(Tdim / BQ, Bdim * Hn);            // 32 x 32
    attn_kernel<<<ga, 128, A_SMEM_BYTES>>>(out);
}